// round 1
// baseline (speedup 1.0000x reference)
#include <cuda_runtime.h>

#define SEQ 512
#define HIDDEN 512
#define NHEAD 8
#define HD 64

// Scratch (static __device__, no allocation)
__device__ float g_q[SEQ * HIDDEN];
__device__ float g_k[SEQ * HIDDEN];
__device__ float g_v[SEQ * HIDDEN];
__device__ float g_ctx[4][SEQ * HIDDEN];   // 4 j-split partial contexts

// ---------------------------------------------------------------------------
// GEMM NT: C[i][o] = sum_h A[i][h] * W[o][h] + b[o]
// 64x64 tile, BK=16, 256 threads, 4x4 microtile, transposed smem ([h][row]).
// ---------------------------------------------------------------------------
__global__ __launch_bounds__(256) void qkv_kernel(
    const float* __restrict__ X,
    const float* __restrict__ Wq, const float* __restrict__ bq,
    const float* __restrict__ Wk, const float* __restrict__ bk,
    const float* __restrict__ Wv, const float* __restrict__ bv)
{
    __shared__ float As[16][68];
    __shared__ float Bs[16][68];

    const float* W;
    const float* bias;
    float* out;
    if (blockIdx.z == 0)      { W = Wq; bias = bq; out = g_q; }
    else if (blockIdx.z == 1) { W = Wk; bias = bk; out = g_k; }
    else                      { W = Wv; bias = bv; out = g_v; }

    int t = threadIdx.x;
    int row0 = blockIdx.y * 64;
    int col0 = blockIdx.x * 64;
    int lr = t >> 2, lc = t & 3;   // loader: row, float4-col
    int ty = t >> 4, tx = t & 15;  // compute: i-group, o-group

    float acc[4][4];
#pragma unroll
    for (int a = 0; a < 4; a++)
#pragma unroll
        for (int b = 0; b < 4; b++) acc[a][b] = 0.0f;

    for (int hb = 0; hb < HIDDEN; hb += 16) {
        float4 av = *(const float4*)(X + (row0 + lr) * HIDDEN + hb + lc * 4);
        float4 wv = *(const float4*)(W + (col0 + lr) * HIDDEN + hb + lc * 4);
        __syncthreads();
        As[lc * 4 + 0][lr] = av.x; As[lc * 4 + 1][lr] = av.y;
        As[lc * 4 + 2][lr] = av.z; As[lc * 4 + 3][lr] = av.w;
        Bs[lc * 4 + 0][lr] = wv.x; Bs[lc * 4 + 1][lr] = wv.y;
        Bs[lc * 4 + 2][lr] = wv.z; Bs[lc * 4 + 3][lr] = wv.w;
        __syncthreads();
#pragma unroll
        for (int h = 0; h < 16; h++) {
            float4 a4 = *(const float4*)&As[h][ty * 4];
            float4 b4 = *(const float4*)&Bs[h][tx * 4];
            float a[4] = {a4.x, a4.y, a4.z, a4.w};
            float b[4] = {b4.x, b4.y, b4.z, b4.w};
#pragma unroll
            for (int mi = 0; mi < 4; mi++)
#pragma unroll
                for (int ni = 0; ni < 4; ni++)
                    acc[mi][ni] = fmaf(a[mi], b[ni], acc[mi][ni]);
        }
    }

    float4 bv4 = *(const float4*)(bias + col0 + tx * 4);
#pragma unroll
    for (int mi = 0; mi < 4; mi++) {
        float4 o = make_float4(acc[mi][0] + bv4.x, acc[mi][1] + bv4.y,
                               acc[mi][2] + bv4.z, acc[mi][3] + bv4.w);
        *(float4*)(out + (row0 + ty * 4 + mi) * HIDDEN + col0 + tx * 4) = o;
    }
}

// ---------------------------------------------------------------------------
// Inhibitor: per (head, i-tile of 64, j-split of 128)
//   z[i,j] = coef*(|q_i|^2 + |k_j|^2 - 2 q.k) + zc + (1-mask[j])*1e10
//   ctx_part[i,k] += sum_j relu(v[j,k] - z[i,j])
// ---------------------------------------------------------------------------
__global__ __launch_bounds__(256) void inhib_kernel(const float* __restrict__ mask,
                                                    const float* __restrict__ gamma)
{
    __shared__ float qs[64][68];   // [d][i]  (transposed q tile)
    __shared__ float ks[32][68];   // [j][d]
    __shared__ float vs[32][64];   // [j][k]
    __shared__ float zs[64][33];   // [i][j]
    __shared__ float q2s[64];      // coef * |q_i|^2
    __shared__ float kt[32];       // coef*|k_j|^2 + zc + mask term

    int t = threadIdx.x;
    int itile = blockIdx.x, head = blockIdx.y, js = blockIdx.z;
    int i0 = itile * 64;

    float g = gamma[0];
    float gs = g * 8.0f;                 // g * sqrt(D), D=64
    float coef = 15.0f / (16.0f * gs);
    float zc = 12.0f / gs;               // (3*D/16) / (g*sqrt(D))
    float m2c = -2.0f * coef;

    // load q tile transposed: qs[d][i]
    {
        int lr = t >> 2, lc = t & 3;
#pragma unroll
        for (int cc = 0; cc < 4; cc++) {
            int c4 = lc * 4 + cc;
            float4 f = *(const float4*)(g_q + (i0 + lr) * HIDDEN + head * HD + c4 * 4);
            qs[c4 * 4 + 0][lr] = f.x; qs[c4 * 4 + 1][lr] = f.y;
            qs[c4 * 4 + 2][lr] = f.z; qs[c4 * 4 + 3][lr] = f.w;
        }
    }
    __syncthreads();
    if (t < 64) {
        float s = 0.0f;
#pragma unroll 8
        for (int d = 0; d < 64; d++) { float q = qs[d][t]; s = fmaf(q, q, s); }
        q2s[t] = coef * s;
    }

    float acc[16];
#pragma unroll
    for (int x = 0; x < 16; x++) acc[x] = 0.0f;

    int il = t >> 2, kq = t & 3;   // accum mapping: i-local, k-quarter
    int ti = t & 15, tj = t >> 4;  // z-phase mapping: i-group, j-pair

    for (int c = 0; c < 4; c++) {
        int j0 = js * 128 + c * 32;
        __syncthreads();  // protects ks/vs/zs reuse; orders q2s on first pass
        {
            int jr = t >> 3, seg = t & 7;
#pragma unroll
            for (int e = 0; e < 2; e++) {
                int c4 = seg * 2 + e;
                float4 kf = *(const float4*)(g_k + (j0 + jr) * HIDDEN + head * HD + c4 * 4);
                *(float4*)&ks[jr][c4 * 4] = kf;
                float4 vf = *(const float4*)(g_v + (j0 + jr) * HIDDEN + head * HD + c4 * 4);
                *(float4*)&vs[jr][c4 * 4] = vf;
            }
        }
        __syncthreads();
        if (t < 32) {
            float s = 0.0f;
#pragma unroll 8
            for (int d = 0; d < 64; d++) { float k = ks[t][d]; s = fmaf(k, k, s); }
            kt[t] = fmaf(coef, s, zc + (1.0f - mask[j0 + t]) * 1e10f);
        }
        __syncthreads();

        // z phase: each thread computes z for 4 i's x 2 j's
        {
            float dot[4][2];
#pragma unroll
            for (int a = 0; a < 4; a++) { dot[a][0] = 0.0f; dot[a][1] = 0.0f; }
#pragma unroll 8
            for (int d = 0; d < 64; d++) {
                float4 a4 = *(const float4*)&qs[d][ti * 4];
                float k0 = ks[tj * 2 + 0][d];
                float k1 = ks[tj * 2 + 1][d];
                dot[0][0] = fmaf(a4.x, k0, dot[0][0]);
                dot[0][1] = fmaf(a4.x, k1, dot[0][1]);
                dot[1][0] = fmaf(a4.y, k0, dot[1][0]);
                dot[1][1] = fmaf(a4.y, k1, dot[1][1]);
                dot[2][0] = fmaf(a4.z, k0, dot[2][0]);
                dot[2][1] = fmaf(a4.z, k1, dot[2][1]);
                dot[3][0] = fmaf(a4.w, k0, dot[3][0]);
                dot[3][1] = fmaf(a4.w, k1, dot[3][1]);
            }
#pragma unroll
            for (int mi = 0; mi < 4; mi++) {
                float qt = q2s[ti * 4 + mi];
#pragma unroll
                for (int jj = 0; jj < 2; jj++) {
                    zs[ti * 4 + mi][tj * 2 + jj] =
                        fmaf(m2c, dot[mi][jj], qt + kt[tj * 2 + jj]);
                }
            }
        }
        __syncthreads();

        // accumulation phase: i fixed per thread, 16 k's in registers
#pragma unroll 2
        for (int jj = 0; jj < 32; jj++) {
            float z = zs[il][jj];
#pragma unroll
            for (int cc = 0; cc < 4; cc++) {
                float4 v4 = *(const float4*)&vs[jj][kq * 16 + cc * 4];
                acc[cc * 4 + 0] += fmaxf(v4.x - z, 0.0f);
                acc[cc * 4 + 1] += fmaxf(v4.y - z, 0.0f);
                acc[cc * 4 + 2] += fmaxf(v4.z - z, 0.0f);
                acc[cc * 4 + 3] += fmaxf(v4.w - z, 0.0f);
            }
        }
    }

    float* outp = g_ctx[js] + (i0 + il) * HIDDEN + head * HD + kq * 16;
#pragma unroll
    for (int cc = 0; cc < 4; cc++) {
        *(float4*)(outp + cc * 4) = make_float4(acc[cc * 4 + 0], acc[cc * 4 + 1],
                                                acc[cc * 4 + 2], acc[cc * 4 + 3]);
    }
}

// ---------------------------------------------------------------------------
// Output projection: out = (sum_p ctx_part[p]) @ Wo^T + bo
// ---------------------------------------------------------------------------
__global__ __launch_bounds__(256) void out_kernel(const float* __restrict__ Wo,
                                                  const float* __restrict__ bo,
                                                  float* __restrict__ out)
{
    __shared__ float As[16][68];
    __shared__ float Bs[16][68];

    int t = threadIdx.x;
    int row0 = blockIdx.y * 64;
    int col0 = blockIdx.x * 64;
    int lr = t >> 2, lc = t & 3;
    int ty = t >> 4, tx = t & 15;

    float acc[4][4];
#pragma unroll
    for (int a = 0; a < 4; a++)
#pragma unroll
        for (int b = 0; b < 4; b++) acc[a][b] = 0.0f;

    for (int hb = 0; hb < HIDDEN; hb += 16) {
        int aoff = (row0 + lr) * HIDDEN + hb + lc * 4;
        float4 a0 = *(const float4*)(g_ctx[0] + aoff);
        float4 a1 = *(const float4*)(g_ctx[1] + aoff);
        float4 a2 = *(const float4*)(g_ctx[2] + aoff);
        float4 a3 = *(const float4*)(g_ctx[3] + aoff);
        float4 av = make_float4(a0.x + a1.x + a2.x + a3.x,
                                a0.y + a1.y + a2.y + a3.y,
                                a0.z + a1.z + a2.z + a3.z,
                                a0.w + a1.w + a2.w + a3.w);
        float4 wv = *(const float4*)(Wo + (col0 + lr) * HIDDEN + hb + lc * 4);
        __syncthreads();
        As[lc * 4 + 0][lr] = av.x; As[lc * 4 + 1][lr] = av.y;
        As[lc * 4 + 2][lr] = av.z; As[lc * 4 + 3][lr] = av.w;
        Bs[lc * 4 + 0][lr] = wv.x; Bs[lc * 4 + 1][lr] = wv.y;
        Bs[lc * 4 + 2][lr] = wv.z; Bs[lc * 4 + 3][lr] = wv.w;
        __syncthreads();
#pragma unroll
        for (int h = 0; h < 16; h++) {
            float4 a4 = *(const float4*)&As[h][ty * 4];
            float4 b4 = *(const float4*)&Bs[h][tx * 4];
            float a[4] = {a4.x, a4.y, a4.z, a4.w};
            float b[4] = {b4.x, b4.y, b4.z, b4.w};
#pragma unroll
            for (int mi = 0; mi < 4; mi++)
#pragma unroll
                for (int ni = 0; ni < 4; ni++)
                    acc[mi][ni] = fmaf(a[mi], b[ni], acc[mi][ni]);
        }
    }

    float4 bv4 = *(const float4*)(bo + col0 + tx * 4);
#pragma unroll
    for (int mi = 0; mi < 4; mi++) {
        float4 o = make_float4(acc[mi][0] + bv4.x, acc[mi][1] + bv4.y,
                               acc[mi][2] + bv4.z, acc[mi][3] + bv4.w);
        *(float4*)(out + (row0 + ty * 4 + mi) * HIDDEN + col0 + tx * 4) = o;
    }
}

extern "C" void kernel_launch(void* const* d_in, const int* in_sizes, int n_in,
                              void* d_out, int out_size)
{
    const float* X     = (const float*)d_in[0];
    const float* mask  = (const float*)d_in[1];
    const float* Wq    = (const float*)d_in[2];
    const float* bq    = (const float*)d_in[3];
    const float* Wk    = (const float*)d_in[4];
    const float* bk    = (const float*)d_in[5];
    const float* Wv    = (const float*)d_in[6];
    const float* bv    = (const float*)d_in[7];
    const float* Wo    = (const float*)d_in[8];
    const float* bo    = (const float*)d_in[9];
    const float* gamma = (const float*)d_in[10];
    float* out = (float*)d_out;

    qkv_kernel<<<dim3(8, 8, 3), 256>>>(X, Wq, bq, Wk, bk, Wv, bv);
    inhib_kernel<<<dim3(8, 8, 4), 256>>>(mask, gamma);
    out_kernel<<<dim3(8, 8), 256>>>(Wo, bo, out);
}

// round 2
// speedup vs baseline: 1.0308x; 1.0308x over previous
#include <cuda_runtime.h>

#define SEQ 512
#define HIDDEN 512
#define NHEAD 8
#define HD 64

// Scratch (static __device__, no allocation)
__device__ float g_q[SEQ * HIDDEN];
__device__ float g_k[SEQ * HIDDEN];
__device__ float g_v[SEQ * HIDDEN];
__device__ float g_ctx[4][SEQ * HIDDEN];   // 4 j-split partial contexts

// ---------------------------------------------------------------------------
// GEMM NT: C[i][o] = sum_h A[i][h] * W[o][h] + b[o]
// 64x64 tile, BK=16, 256 threads, 4x4 microtile, transposed smem ([h][row]).
// Double-buffered smem + register prefetch: ONE sync per K-block.
// ---------------------------------------------------------------------------
__global__ __launch_bounds__(256) void qkv_kernel(
    const float* __restrict__ X,
    const float* __restrict__ Wq, const float* __restrict__ bq,
    const float* __restrict__ Wk, const float* __restrict__ bk,
    const float* __restrict__ Wv, const float* __restrict__ bv)
{
    __shared__ float As[2][16][68];
    __shared__ float Bs[2][16][68];

    const float* W;
    const float* bias;
    float* out;
    if (blockIdx.z == 0)      { W = Wq; bias = bq; out = g_q; }
    else if (blockIdx.z == 1) { W = Wk; bias = bk; out = g_k; }
    else                      { W = Wv; bias = bv; out = g_v; }

    int t = threadIdx.x;
    int row0 = blockIdx.y * 64;
    int col0 = blockIdx.x * 64;
    int lr = t >> 2, lc = t & 3;   // loader: row, float4-col
    int ty = t >> 4, tx = t & 15;  // compute: i-group, o-group

    float acc[4][4];
#pragma unroll
    for (int a = 0; a < 4; a++)
#pragma unroll
        for (int b = 0; b < 4; b++) acc[a][b] = 0.0f;

    const float* Aptr = X + (row0 + lr) * HIDDEN + lc * 4;
    const float* Bptr = W + (col0 + lr) * HIDDEN + lc * 4;

    float4 av = *(const float4*)(Aptr);
    float4 wv = *(const float4*)(Bptr);
    As[0][lc * 4 + 0][lr] = av.x; As[0][lc * 4 + 1][lr] = av.y;
    As[0][lc * 4 + 2][lr] = av.z; As[0][lc * 4 + 3][lr] = av.w;
    Bs[0][lc * 4 + 0][lr] = wv.x; Bs[0][lc * 4 + 1][lr] = wv.y;
    Bs[0][lc * 4 + 2][lr] = wv.z; Bs[0][lc * 4 + 3][lr] = wv.w;
    __syncthreads();

    int buf = 0;
#pragma unroll 1
    for (int kb = 0; kb < 32; kb++) {
        if (kb < 31) {
            av = *(const float4*)(Aptr + (kb + 1) * 16);
            wv = *(const float4*)(Bptr + (kb + 1) * 16);
        }
#pragma unroll
        for (int h = 0; h < 16; h++) {
            float4 a4 = *(const float4*)&As[buf][h][ty * 4];
            float4 b4 = *(const float4*)&Bs[buf][h][tx * 4];
            float a[4] = {a4.x, a4.y, a4.z, a4.w};
            float b[4] = {b4.x, b4.y, b4.z, b4.w};
#pragma unroll
            for (int mi = 0; mi < 4; mi++)
#pragma unroll
                for (int ni = 0; ni < 4; ni++)
                    acc[mi][ni] = fmaf(a[mi], b[ni], acc[mi][ni]);
        }
        if (kb < 31) {
            int nb = buf ^ 1;
            As[nb][lc * 4 + 0][lr] = av.x; As[nb][lc * 4 + 1][lr] = av.y;
            As[nb][lc * 4 + 2][lr] = av.z; As[nb][lc * 4 + 3][lr] = av.w;
            Bs[nb][lc * 4 + 0][lr] = wv.x; Bs[nb][lc * 4 + 1][lr] = wv.y;
            Bs[nb][lc * 4 + 2][lr] = wv.z; Bs[nb][lc * 4 + 3][lr] = wv.w;
            __syncthreads();
            buf = nb;
        }
    }

    float4 bv4 = *(const float4*)(bias + col0 + tx * 4);
#pragma unroll
    for (int mi = 0; mi < 4; mi++) {
        float4 o = make_float4(acc[mi][0] + bv4.x, acc[mi][1] + bv4.y,
                               acc[mi][2] + bv4.z, acc[mi][3] + bv4.w);
        *(float4*)(out + (row0 + ty * 4 + mi) * HIDDEN + col0 + tx * 4) = o;
    }
}

// ---------------------------------------------------------------------------
// Inhibitor: per (head, i-tile of 64, j-split of 128)
//   z[i,j] = coef*(|q_i|^2 + |k_j|^2 - 2 q.k) + zc + (1-mask[j])*1e10
// relu trick: relu(v - z) = max(v, z) - z  -->
//   ctx[i,k] = sum_j max(v[j,k], z[i,j]) - sum_j z[i,j]
// Inner loop: 2 fp instructions per element (FMNMX + FADD).
// Next chunk's k/v prefetched in registers during compute.
// ---------------------------------------------------------------------------
__global__ __launch_bounds__(256) void inhib_kernel(const float* __restrict__ mask,
                                                    const float* __restrict__ gamma)
{
    __shared__ float qs[64][68];   // [d][i]  (transposed q tile)
    __shared__ float ks[32][68];   // [j][d]
    __shared__ float vs[32][64];   // [j][k]
    __shared__ float zs[64][33];   // [i][j]
    __shared__ float q2s[64];      // coef * |q_i|^2
    __shared__ float kt[32];       // coef*|k_j|^2 + zc + mask term

    int t = threadIdx.x;
    int itile = blockIdx.x, head = blockIdx.y, js = blockIdx.z;
    int i0 = itile * 64;

    float g = gamma[0];
    float gs = g * 8.0f;                 // g * sqrt(D), D=64
    float coef = 15.0f / (16.0f * gs);
    float zc = 12.0f / gs;               // (3*D/16) / (g*sqrt(D))
    float m2c = -2.0f * coef;

    // load q tile transposed: qs[d][i]
    {
        int lr = t >> 2, lc = t & 3;
#pragma unroll
        for (int cc = 0; cc < 4; cc++) {
            int c4 = lc * 4 + cc;
            float4 f = *(const float4*)(g_q + (i0 + lr) * HIDDEN + head * HD + c4 * 4);
            qs[c4 * 4 + 0][lr] = f.x; qs[c4 * 4 + 1][lr] = f.y;
            qs[c4 * 4 + 2][lr] = f.z; qs[c4 * 4 + 3][lr] = f.w;
        }
    }
    __syncthreads();
    if (t < 64) {
        float s = 0.0f;
#pragma unroll 8
        for (int d = 0; d < 64; d++) { float q = qs[d][t]; s = fmaf(q, q, s); }
        q2s[t] = coef * s;
    }

    float acc[16];
#pragma unroll
    for (int x = 0; x < 16; x++) acc[x] = 0.0f;
    float accz = 0.0f;

    int il = t >> 2, kq = t & 3;   // accum mapping: i-local, k-quarter
    int ti = t & 15, tj = t >> 4;  // z-phase mapping: i-group, j-pair

    // prefetch chunk 0 of k/v into registers
    int jr = t >> 3, seg = t & 7;  // jr 0..31 (j row), seg 0..7 (8-float segment? 2x float4)
    const float* kp = g_k + (js * 128 + jr) * HIDDEN + head * HD + seg * 8;
    const float* vp = g_v + (js * 128 + jr) * HIDDEN + head * HD + seg * 8;
    float4 kf0 = *(const float4*)(kp);
    float4 kf1 = *(const float4*)(kp + 4);
    float4 vf0 = *(const float4*)(vp);
    float4 vf1 = *(const float4*)(vp + 4);

#pragma unroll 1
    for (int c = 0; c < 4; c++) {
        int j0 = js * 128 + c * 32;
        __syncthreads();  // prev chunk's relu done reading ks/vs; q2s visible (c=0)
        *(float4*)&ks[jr][seg * 8]     = kf0;
        *(float4*)&ks[jr][seg * 8 + 4] = kf1;
        *(float4*)&vs[jr][seg * 8]     = vf0;
        *(float4*)&vs[jr][seg * 8 + 4] = vf1;
        if (c < 3) {  // prefetch next chunk while we compute this one
            kf0 = *(const float4*)(kp + (c + 1) * 32 * HIDDEN);
            kf1 = *(const float4*)(kp + (c + 1) * 32 * HIDDEN + 4);
            vf0 = *(const float4*)(vp + (c + 1) * 32 * HIDDEN);
            vf1 = *(const float4*)(vp + (c + 1) * 32 * HIDDEN + 4);
        }
        __syncthreads();
        if (t < 32) {
            float s = 0.0f;
#pragma unroll 8
            for (int d = 0; d < 64; d++) { float k = ks[t][d]; s = fmaf(k, k, s); }
            kt[t] = fmaf(coef, s, zc + (1.0f - mask[j0 + t]) * 1e10f);
        }
        __syncthreads();

        // z phase: each thread computes z for 4 i's x 2 j's
        {
            float dot[4][2];
#pragma unroll
            for (int a = 0; a < 4; a++) { dot[a][0] = 0.0f; dot[a][1] = 0.0f; }
#pragma unroll 8
            for (int d = 0; d < 64; d++) {
                float4 a4 = *(const float4*)&qs[d][ti * 4];
                float k0 = ks[tj * 2 + 0][d];
                float k1 = ks[tj * 2 + 1][d];
                dot[0][0] = fmaf(a4.x, k0, dot[0][0]);
                dot[0][1] = fmaf(a4.x, k1, dot[0][1]);
                dot[1][0] = fmaf(a4.y, k0, dot[1][0]);
                dot[1][1] = fmaf(a4.y, k1, dot[1][1]);
                dot[2][0] = fmaf(a4.z, k0, dot[2][0]);
                dot[2][1] = fmaf(a4.z, k1, dot[2][1]);
                dot[3][0] = fmaf(a4.w, k0, dot[3][0]);
                dot[3][1] = fmaf(a4.w, k1, dot[3][1]);
            }
#pragma unroll
            for (int mi = 0; mi < 4; mi++) {
                float qt = q2s[ti * 4 + mi];
#pragma unroll
                for (int jj = 0; jj < 2; jj++) {
                    zs[ti * 4 + mi][tj * 2 + jj] =
                        fmaf(m2c, dot[mi][jj], qt + kt[tj * 2 + jj]);
                }
            }
        }
        __syncthreads();

        // accumulation phase: ctx += max(v, z); accz += z
#pragma unroll 4
        for (int jj = 0; jj < 32; jj++) {
            float z = zs[il][jj];
            accz += z;
#pragma unroll
            for (int cc = 0; cc < 4; cc++) {
                float4 v4 = *(const float4*)&vs[jj][kq * 16 + cc * 4];
                acc[cc * 4 + 0] += fmaxf(v4.x, z);
                acc[cc * 4 + 1] += fmaxf(v4.y, z);
                acc[cc * 4 + 2] += fmaxf(v4.z, z);
                acc[cc * 4 + 3] += fmaxf(v4.w, z);
            }
        }
    }

    float* outp = g_ctx[js] + (i0 + il) * HIDDEN + head * HD + kq * 16;
#pragma unroll
    for (int cc = 0; cc < 4; cc++) {
        *(float4*)(outp + cc * 4) = make_float4(acc[cc * 4 + 0] - accz,
                                                acc[cc * 4 + 1] - accz,
                                                acc[cc * 4 + 2] - accz,
                                                acc[cc * 4 + 3] - accz);
    }
}

// ---------------------------------------------------------------------------
// Output projection: out = (sum_p ctx_part[p]) @ Wo^T + bo
// Double-buffered like qkv_kernel.
// ---------------------------------------------------------------------------
__global__ __launch_bounds__(256) void out_kernel(const float* __restrict__ Wo,
                                                  const float* __restrict__ bo,
                                                  float* __restrict__ out)
{
    __shared__ float As[2][16][68];
    __shared__ float Bs[2][16][68];

    int t = threadIdx.x;
    int row0 = blockIdx.y * 64;
    int col0 = blockIdx.x * 64;
    int lr = t >> 2, lc = t & 3;
    int ty = t >> 4, tx = t & 15;

    float acc[4][4];
#pragma unroll
    for (int a = 0; a < 4; a++)
#pragma unroll
        for (int b = 0; b < 4; b++) acc[a][b] = 0.0f;

    int aoff0 = (row0 + lr) * HIDDEN + lc * 4;
    const float* Bptr = Wo + (col0 + lr) * HIDDEN + lc * 4;

    float4 a0 = *(const float4*)(g_ctx[0] + aoff0);
    float4 a1 = *(const float4*)(g_ctx[1] + aoff0);
    float4 a2 = *(const float4*)(g_ctx[2] + aoff0);
    float4 a3 = *(const float4*)(g_ctx[3] + aoff0);
    float4 av = make_float4(a0.x + a1.x + a2.x + a3.x,
                            a0.y + a1.y + a2.y + a3.y,
                            a0.z + a1.z + a2.z + a3.z,
                            a0.w + a1.w + a2.w + a3.w);
    float4 wv = *(const float4*)(Bptr);
    As[0][lc * 4 + 0][lr] = av.x; As[0][lc * 4 + 1][lr] = av.y;
    As[0][lc * 4 + 2][lr] = av.z; As[0][lc * 4 + 3][lr] = av.w;
    Bs[0][lc * 4 + 0][lr] = wv.x; Bs[0][lc * 4 + 1][lr] = wv.y;
    Bs[0][lc * 4 + 2][lr] = wv.z; Bs[0][lc * 4 + 3][lr] = wv.w;
    __syncthreads();

    int buf = 0;
#pragma unroll 1
    for (int kb = 0; kb < 32; kb++) {
        if (kb < 31) {
            int aoff = aoff0 + (kb + 1) * 16;
            a0 = *(const float4*)(g_ctx[0] + aoff);
            a1 = *(const float4*)(g_ctx[1] + aoff);
            a2 = *(const float4*)(g_ctx[2] + aoff);
            a3 = *(const float4*)(g_ctx[3] + aoff);
            av = make_float4(a0.x + a1.x + a2.x + a3.x,
                             a0.y + a1.y + a2.y + a3.y,
                             a0.z + a1.z + a2.z + a3.z,
                             a0.w + a1.w + a2.w + a3.w);
            wv = *(const float4*)(Bptr + (kb + 1) * 16);
        }
#pragma unroll
        for (int h = 0; h < 16; h++) {
            float4 a4 = *(const float4*)&As[buf][h][ty * 4];
            float4 b4 = *(const float4*)&Bs[buf][h][tx * 4];
            float a[4] = {a4.x, a4.y, a4.z, a4.w};
            float b[4] = {b4.x, b4.y, b4.z, b4.w};
#pragma unroll
            for (int mi = 0; mi < 4; mi++)
#pragma unroll
                for (int ni = 0; ni < 4; ni++)
                    acc[mi][ni] = fmaf(a[mi], b[ni], acc[mi][ni]);
        }
        if (kb < 31) {
            int nb = buf ^ 1;
            As[nb][lc * 4 + 0][lr] = av.x; As[nb][lc * 4 + 1][lr] = av.y;
            As[nb][lc * 4 + 2][lr] = av.z; As[nb][lc * 4 + 3][lr] = av.w;
            Bs[nb][lc * 4 + 0][lr] = wv.x; Bs[nb][lc * 4 + 1][lr] = wv.y;
            Bs[nb][lc * 4 + 2][lr] = wv.z; Bs[nb][lc * 4 + 3][lr] = wv.w;
            __syncthreads();
            buf = nb;
        }
    }

    float4 bv4 = *(const float4*)(bo + col0 + tx * 4);
#pragma unroll
    for (int mi = 0; mi < 4; mi++) {
        float4 o = make_float4(acc[mi][0] + bv4.x, acc[mi][1] + bv4.y,
                               acc[mi][2] + bv4.z, acc[mi][3] + bv4.w);
        *(float4*)(out + (row0 + ty * 4 + mi) * HIDDEN + col0 + tx * 4) = o;
    }
}

extern "C" void kernel_launch(void* const* d_in, const int* in_sizes, int n_in,
                              void* d_out, int out_size)
{
    const float* X     = (const float*)d_in[0];
    const float* mask  = (const float*)d_in[1];
    const float* Wq    = (const float*)d_in[2];
    const float* bq    = (const float*)d_in[3];
    const float* Wk    = (const float*)d_in[4];
    const float* bk    = (const float*)d_in[5];
    const float* Wv    = (const float*)d_in[6];
    const float* bv    = (const float*)d_in[7];
    const float* Wo    = (const float*)d_in[8];
    const float* bo    = (const float*)d_in[9];
    const float* gamma = (const float*)d_in[10];
    float* out = (float*)d_out;

    qkv_kernel<<<dim3(8, 8, 3), 256>>>(X, Wq, bq, Wk, bk, Wv, bv);
    inhib_kernel<<<dim3(8, 8, 4), 256>>>(mask, gamma);
    out_kernel<<<dim3(8, 8), 256>>>(Wo, bo, out);
}

// round 3
// speedup vs baseline: 1.1994x; 1.1636x over previous
#include <cuda_runtime.h>

#define SEQ 512
#define HIDDEN 512
#define HD 64

// Scratch (static __device__, no allocation)
__device__ float g_q[SEQ * HIDDEN];
__device__ float g_k[SEQ * HIDDEN];
__device__ float g_v[SEQ * HIDDEN];
__device__ float g_ctx[4][SEQ * HIDDEN];   // 4 j-split partial contexts

// ---------------------------------------------------------------------------
// GEMM NT: C[i][o] = sum_h A[i][h] * W[o][h] + b[o]
// 64(M) x 32(N) tile, BK=32, 128 threads, 4x4 microtile, double-buffered.
// ---------------------------------------------------------------------------
__global__ __launch_bounds__(128) void qkv_kernel(
    const float* __restrict__ X,
    const float* __restrict__ Wq, const float* __restrict__ bq,
    const float* __restrict__ Wk, const float* __restrict__ bk,
    const float* __restrict__ Wv, const float* __restrict__ bv)
{
    __shared__ float As[2][32][72];  // [k][i], 16B-aligned rows
    __shared__ float Bs[2][32][36];  // [k][o]

    const float* W;
    const float* bias;
    float* out;
    if (blockIdx.z == 0)      { W = Wq; bias = bq; out = g_q; }
    else if (blockIdx.z == 1) { W = Wk; bias = bk; out = g_k; }
    else                      { W = Wv; bias = bv; out = g_v; }

    int t = threadIdx.x;
    int row0 = blockIdx.y * 64;
    int col0 = blockIdx.x * 32;
    int lrA = t >> 1, lcA = t & 1;   // A loader: row (0..63), k-half
    int lrB = t >> 2, lcB = t & 3;   // B loader: o-row (0..31), k-f4
    int ty = t >> 3, tx = t & 7;     // compute: i-group (0..15), o-group (0..7)

    float acc[4][4];
#pragma unroll
    for (int a = 0; a < 4; a++)
#pragma unroll
        for (int b = 0; b < 4; b++) acc[a][b] = 0.0f;

    const float* Ap = X + (row0 + lrA) * HIDDEN + lcA * 16;
    const float* Bp = W + (col0 + lrB) * HIDDEN + lcB * 4;

    float4 a[4], b[2];
#pragma unroll
    for (int c = 0; c < 4; c++) a[c] = *(const float4*)(Ap + c * 4);
#pragma unroll
    for (int s = 0; s < 2; s++) b[s] = *(const float4*)(Bp + s * 16);

#pragma unroll
    for (int c = 0; c < 4; c++) {
        int k = lcA * 16 + c * 4;
        As[0][k + 0][lrA] = a[c].x; As[0][k + 1][lrA] = a[c].y;
        As[0][k + 2][lrA] = a[c].z; As[0][k + 3][lrA] = a[c].w;
    }
#pragma unroll
    for (int s = 0; s < 2; s++) {
        int k = (lcB + 4 * s) * 4;
        Bs[0][k + 0][lrB] = b[s].x; Bs[0][k + 1][lrB] = b[s].y;
        Bs[0][k + 2][lrB] = b[s].z; Bs[0][k + 3][lrB] = b[s].w;
    }
    __syncthreads();

    int buf = 0;
#pragma unroll 1
    for (int kb = 0; kb < 16; kb++) {
        if (kb < 15) {
#pragma unroll
            for (int c = 0; c < 4; c++) a[c] = *(const float4*)(Ap + (kb + 1) * 32 + c * 4);
#pragma unroll
            for (int s = 0; s < 2; s++) b[s] = *(const float4*)(Bp + (kb + 1) * 32 + s * 16);
        }
#pragma unroll
        for (int h = 0; h < 32; h++) {
            float4 a4 = *(const float4*)&As[buf][h][ty * 4];
            float4 b4 = *(const float4*)&Bs[buf][h][tx * 4];
            float av[4] = {a4.x, a4.y, a4.z, a4.w};
            float bv2[4] = {b4.x, b4.y, b4.z, b4.w};
#pragma unroll
            for (int mi = 0; mi < 4; mi++)
#pragma unroll
                for (int ni = 0; ni < 4; ni++)
                    acc[mi][ni] = fmaf(av[mi], bv2[ni], acc[mi][ni]);
        }
        if (kb < 15) {
            int nb = buf ^ 1;
#pragma unroll
            for (int c = 0; c < 4; c++) {
                int k = lcA * 16 + c * 4;
                As[nb][k + 0][lrA] = a[c].x; As[nb][k + 1][lrA] = a[c].y;
                As[nb][k + 2][lrA] = a[c].z; As[nb][k + 3][lrA] = a[c].w;
            }
#pragma unroll
            for (int s = 0; s < 2; s++) {
                int k = (lcB + 4 * s) * 4;
                Bs[nb][k + 0][lrB] = b[s].x; Bs[nb][k + 1][lrB] = b[s].y;
                Bs[nb][k + 2][lrB] = b[s].z; Bs[nb][k + 3][lrB] = b[s].w;
            }
            __syncthreads();
            buf = nb;
        }
    }

    float4 bv4 = *(const float4*)(bias + col0 + tx * 4);
#pragma unroll
    for (int mi = 0; mi < 4; mi++) {
        float4 o = make_float4(acc[mi][0] + bv4.x, acc[mi][1] + bv4.y,
                               acc[mi][2] + bv4.z, acc[mi][3] + bv4.w);
        *(float4*)(out + (row0 + ty * 4 + mi) * HIDDEN + col0 + tx * 4) = o;
    }
}

// ---------------------------------------------------------------------------
// Inhibitor: CTA = (i-tile of 32, head, j-split of 128), 128 threads.
//   z[i,j] = coef*(|q_i|^2 + |k_j|^2 - 2 q.k) + zc + (1-mask[j])*1e10
//   ctx[i,k] = sum_j max(v[j,k], z[i,j]) - sum_j z[i,j]      (relu trick)
// |k|^2 partials computed from prefetch registers at store time (no extra
// phase); kt assembled per z-thread from partials; mask staged once in smem.
// ---------------------------------------------------------------------------
__global__ __launch_bounds__(128) void inhib_kernel(const float* __restrict__ mask,
                                                    const float* __restrict__ gamma)
{
    __shared__ float qs[64][36];     // [d][i]  transposed q tile (i: 32)
    __shared__ float ks[32][72];     // [j][d]
    __shared__ float vs[32][72];     // [j][k]
    __shared__ float zs[32][33];     // [i][j]
    __shared__ float q2s[32];        // coef * |q_i|^2
    __shared__ float kps[32][4];     // |k_j|^2 partials
    __shared__ float ms[128];        // (1-mask)*1e10 for this CTA's 128 j's

    int t = threadIdx.x;
    int i0 = blockIdx.x * 32, head = blockIdx.y, js = blockIdx.z;

    float g = gamma[0];
    float gs = g * 8.0f;                 // g * sqrt(D), D=64
    float coef = 15.0f / (16.0f * gs);
    float zc = 12.0f / gs;               // (3*D/16) / (g*sqrt(D))
    float m2c = -2.0f * coef;

    // load q tile transposed: thread (lr=row 0..31, lc=d-quarter)
    {
        int lr = t >> 2, lc = t & 3;
#pragma unroll
        for (int c = 0; c < 4; c++) {
            float4 f = *(const float4*)(g_q + (i0 + lr) * HIDDEN + head * HD + lc * 16 + c * 4);
            int d = lc * 16 + c * 4;
            qs[d + 0][lr] = f.x; qs[d + 1][lr] = f.y;
            qs[d + 2][lr] = f.z; qs[d + 3][lr] = f.w;
        }
    }
    ms[t] = (1.0f - mask[js * 128 + t]) * 1e10f;
    __syncthreads();
    if (t < 32) {
        float s = 0.0f;
#pragma unroll 8
        for (int d = 0; d < 64; d++) { float q = qs[d][t]; s = fmaf(q, q, s); }
        q2s[t] = coef * s;
    }

    // prefetch chunk 0 of k/v into registers: thread (jrow 0..31, lc d-quarter)
    int jrow = t >> 2, lc = t & 3;
    const float* kp = g_k + (js * 128 + jrow) * HIDDEN + head * HD + lc * 16;
    const float* vp = g_v + (js * 128 + jrow) * HIDDEN + head * HD + lc * 16;
    float4 kf[4], vf[4];
#pragma unroll
    for (int c = 0; c < 4; c++) { kf[c] = *(const float4*)(kp + c * 4);
                                  vf[c] = *(const float4*)(vp + c * 4); }

    float acc[16];
#pragma unroll
    for (int x = 0; x < 16; x++) acc[x] = 0.0f;
    float accz = 0.0f;

    int il = t & 31, kq = t >> 5;    // acc mapping: i-local (0..31), k-quarter (0..3)
    int ti = t & 7, tj = t >> 3;     // z mapping: i-group (0..7), j-pair (0..15)

#pragma unroll 1
    for (int c = 0; c < 4; c++) {
        __syncthreads();  // all reads of ks/vs/zs from previous chunk done
        float kp2 = 0.0f;
#pragma unroll
        for (int cc = 0; cc < 4; cc++) {
            *(float4*)&ks[jrow][lc * 16 + cc * 4] = kf[cc];
            kp2 = fmaf(kf[cc].x, kf[cc].x, kp2);
            kp2 = fmaf(kf[cc].y, kf[cc].y, kp2);
            kp2 = fmaf(kf[cc].z, kf[cc].z, kp2);
            kp2 = fmaf(kf[cc].w, kf[cc].w, kp2);
            *(float4*)&vs[jrow][lc * 16 + cc * 4] = vf[cc];
        }
        kps[jrow][lc] = kp2;
        if (c < 3) {  // prefetch next chunk
#pragma unroll
            for (int cc = 0; cc < 4; cc++) {
                kf[cc] = *(const float4*)(kp + (c + 1) * 32 * HIDDEN + cc * 4);
                vf[cc] = *(const float4*)(vp + (c + 1) * 32 * HIDDEN + cc * 4);
            }
        }
        __syncthreads();

        // z phase: 4 i's x 2 j's per thread
        {
            float dot[4][2];
#pragma unroll
            for (int a = 0; a < 4; a++) { dot[a][0] = 0.0f; dot[a][1] = 0.0f; }
#pragma unroll 8
            for (int d = 0; d < 64; d++) {
                float4 a4 = *(const float4*)&qs[d][ti * 4];
                float k0 = ks[tj * 2 + 0][d];
                float k1 = ks[tj * 2 + 1][d];
                dot[0][0] = fmaf(a4.x, k0, dot[0][0]);
                dot[0][1] = fmaf(a4.x, k1, dot[0][1]);
                dot[1][0] = fmaf(a4.y, k0, dot[1][0]);
                dot[1][1] = fmaf(a4.y, k1, dot[1][1]);
                dot[2][0] = fmaf(a4.z, k0, dot[2][0]);
                dot[2][1] = fmaf(a4.z, k1, dot[2][1]);
                dot[3][0] = fmaf(a4.w, k0, dot[3][0]);
                dot[3][1] = fmaf(a4.w, k1, dot[3][1]);
            }
            int j0 = tj * 2, j1 = tj * 2 + 1;
            float kt0 = fmaf(coef, kps[j0][0] + kps[j0][1] + kps[j0][2] + kps[j0][3],
                             zc + ms[c * 32 + j0]);
            float kt1 = fmaf(coef, kps[j1][0] + kps[j1][1] + kps[j1][2] + kps[j1][3],
                             zc + ms[c * 32 + j1]);
#pragma unroll
            for (int mi = 0; mi < 4; mi++) {
                float qt = q2s[ti * 4 + mi];
                zs[ti * 4 + mi][j0] = fmaf(m2c, dot[mi][0], qt + kt0);
                zs[ti * 4 + mi][j1] = fmaf(m2c, dot[mi][1], qt + kt1);
            }
        }
        __syncthreads();

        // accumulation: ctx += max(v, z); accz += z
#pragma unroll 4
        for (int jj = 0; jj < 32; jj++) {
            float z = zs[il][jj];
            accz += z;
#pragma unroll
            for (int cc = 0; cc < 4; cc++) {
                float4 v4 = *(const float4*)&vs[jj][kq * 16 + cc * 4];
                acc[cc * 4 + 0] += fmaxf(v4.x, z);
                acc[cc * 4 + 1] += fmaxf(v4.y, z);
                acc[cc * 4 + 2] += fmaxf(v4.z, z);
                acc[cc * 4 + 3] += fmaxf(v4.w, z);
            }
        }
    }

    float* outp = g_ctx[js] + (i0 + il) * HIDDEN + head * HD + kq * 16;
#pragma unroll
    for (int cc = 0; cc < 4; cc++) {
        *(float4*)(outp + cc * 4) = make_float4(acc[cc * 4 + 0] - accz,
                                                acc[cc * 4 + 1] - accz,
                                                acc[cc * 4 + 2] - accz,
                                                acc[cc * 4 + 3] - accz);
    }
}

// ---------------------------------------------------------------------------
// Output projection: out = (sum_p ctx_part[p]) @ Wo^T + bo
// Same 64x32 / 128-thread double-buffered structure.
// ---------------------------------------------------------------------------
__global__ __launch_bounds__(128) void out_kernel(const float* __restrict__ Wo,
                                                  const float* __restrict__ bo,
                                                  float* __restrict__ out)
{
    __shared__ float As[2][32][72];
    __shared__ float Bs[2][32][36];

    int t = threadIdx.x;
    int row0 = blockIdx.y * 64;
    int col0 = blockIdx.x * 32;
    int lrA = t >> 1, lcA = t & 1;
    int lrB = t >> 2, lcB = t & 3;
    int ty = t >> 3, tx = t & 7;

    float acc[4][4];
#pragma unroll
    for (int a = 0; a < 4; a++)
#pragma unroll
        for (int b = 0; b < 4; b++) acc[a][b] = 0.0f;

    int aoff0 = (row0 + lrA) * HIDDEN + lcA * 16;
    const float* Bp = Wo + (col0 + lrB) * HIDDEN + lcB * 4;

    float4 a[4], b[2];
#pragma unroll
    for (int c = 0; c < 4; c++) {
        float4 s0 = *(const float4*)(g_ctx[0] + aoff0 + c * 4);
        float4 s1 = *(const float4*)(g_ctx[1] + aoff0 + c * 4);
        float4 s2 = *(const float4*)(g_ctx[2] + aoff0 + c * 4);
        float4 s3 = *(const float4*)(g_ctx[3] + aoff0 + c * 4);
        a[c] = make_float4(s0.x + s1.x + s2.x + s3.x, s0.y + s1.y + s2.y + s3.y,
                           s0.z + s1.z + s2.z + s3.z, s0.w + s1.w + s2.w + s3.w);
    }
#pragma unroll
    for (int s = 0; s < 2; s++) b[s] = *(const float4*)(Bp + s * 16);

#pragma unroll
    for (int c = 0; c < 4; c++) {
        int k = lcA * 16 + c * 4;
        As[0][k + 0][lrA] = a[c].x; As[0][k + 1][lrA] = a[c].y;
        As[0][k + 2][lrA] = a[c].z; As[0][k + 3][lrA] = a[c].w;
    }
#pragma unroll
    for (int s = 0; s < 2; s++) {
        int k = (lcB + 4 * s) * 4;
        Bs[0][k + 0][lrB] = b[s].x; Bs[0][k + 1][lrB] = b[s].y;
        Bs[0][k + 2][lrB] = b[s].z; Bs[0][k + 3][lrB] = b[s].w;
    }
    __syncthreads();

    int buf = 0;
#pragma unroll 1
    for (int kb = 0; kb < 16; kb++) {
        if (kb < 15) {
            int aoff = aoff0 + (kb + 1) * 32;
#pragma unroll
            for (int c = 0; c < 4; c++) {
                float4 s0 = *(const float4*)(g_ctx[0] + aoff + c * 4);
                float4 s1 = *(const float4*)(g_ctx[1] + aoff + c * 4);
                float4 s2 = *(const float4*)(g_ctx[2] + aoff + c * 4);
                float4 s3 = *(const float4*)(g_ctx[3] + aoff + c * 4);
                a[c] = make_float4(s0.x + s1.x + s2.x + s3.x, s0.y + s1.y + s2.y + s3.y,
                                   s0.z + s1.z + s2.z + s3.z, s0.w + s1.w + s2.w + s3.w);
            }
#pragma unroll
            for (int s = 0; s < 2; s++) b[s] = *(const float4*)(Bp + (kb + 1) * 32 + s * 16);
        }
#pragma unroll
        for (int h = 0; h < 32; h++) {
            float4 a4 = *(const float4*)&As[buf][h][ty * 4];
            float4 b4 = *(const float4*)&Bs[buf][h][tx * 4];
            float av[4] = {a4.x, a4.y, a4.z, a4.w};
            float bv2[4] = {b4.x, b4.y, b4.z, b4.w};
#pragma unroll
            for (int mi = 0; mi < 4; mi++)
#pragma unroll
                for (int ni = 0; ni < 4; ni++)
                    acc[mi][ni] = fmaf(av[mi], bv2[ni], acc[mi][ni]);
        }
        if (kb < 15) {
            int nb = buf ^ 1;
#pragma unroll
            for (int c = 0; c < 4; c++) {
                int k = lcA * 16 + c * 4;
                As[nb][k + 0][lrA] = a[c].x; As[nb][k + 1][lrA] = a[c].y;
                As[nb][k + 2][lrA] = a[c].z; As[nb][k + 3][lrA] = a[c].w;
            }
#pragma unroll
            for (int s = 0; s < 2; s++) {
                int k = (lcB + 4 * s) * 4;
                Bs[nb][k + 0][lrB] = b[s].x; Bs[nb][k + 1][lrB] = b[s].y;
                Bs[nb][k + 2][lrB] = b[s].z; Bs[nb][k + 3][lrB] = b[s].w;
            }
            __syncthreads();
            buf = nb;
        }
    }

    float4 bv4 = *(const float4*)(bo + col0 + tx * 4);
#pragma unroll
    for (int mi = 0; mi < 4; mi++) {
        float4 o = make_float4(acc[mi][0] + bv4.x, acc[mi][1] + bv4.y,
                               acc[mi][2] + bv4.z, acc[mi][3] + bv4.w);
        *(float4*)(out + (row0 + ty * 4 + mi) * HIDDEN + col0 + tx * 4) = o;
    }
}

extern "C" void kernel_launch(void* const* d_in, const int* in_sizes, int n_in,
                              void* d_out, int out_size)
{
    const float* X     = (const float*)d_in[0];
    const float* mask  = (const float*)d_in[1];
    const float* Wq    = (const float*)d_in[2];
    const float* bq    = (const float*)d_in[3];
    const float* Wk    = (const float*)d_in[4];
    const float* bk    = (const float*)d_in[5];
    const float* Wv    = (const float*)d_in[6];
    const float* bv    = (const float*)d_in[7];
    const float* Wo    = (const float*)d_in[8];
    const float* bo    = (const float*)d_in[9];
    const float* gamma = (const float*)d_in[10];
    float* out = (float*)d_out;

    qkv_kernel<<<dim3(16, 8, 3), 128>>>(X, Wq, bq, Wk, bk, Wv, bv);
    inhib_kernel<<<dim3(16, 8, 4), 128>>>(mask, gamma);
    out_kernel<<<dim3(16, 8), 128>>>(Wo, bo, out);
}

// round 4
// speedup vs baseline: 1.5426x; 1.2861x over previous
#include <cuda_runtime.h>

#define SEQ 512
#define HIDDEN 512
#define HD 64
#define NPART 8

// Scratch (static __device__, no allocation)
__device__ float g_q[SEQ * HIDDEN];
__device__ float g_k[SEQ * HIDDEN];
__device__ float g_v[SEQ * HIDDEN];
__device__ float g_ctx[NPART][SEQ * HIDDEN];
__device__ float g_ctxsum[SEQ * HIDDEN];

// ---------------------------------------------------------------------------
// bf16x3 split helpers.
// hi = exact top-16-bit truncation of f32 (valid bf16), lo = x - hi (exact),
// rounded to bf16. Dropped lo*lo term ~2^-16 relative; kept terms exact-ish.
// Pack convention: lower 16 bits of the u32 = element with the SMALLER k.
// ---------------------------------------------------------------------------
__device__ __forceinline__ void split2(float x0, float x1, unsigned& hi, unsigned& lo)
{
    unsigned u0 = __float_as_uint(x0), u1 = __float_as_uint(x1);
    unsigned h;
    asm("prmt.b32 %0, %1, %2, 0x7632;" : "=r"(h) : "r"(u0), "r"(u1));
    float l0 = x0 - __uint_as_float(u0 & 0xFFFF0000u);
    float l1 = x1 - __uint_as_float(u1 & 0xFFFF0000u);
    unsigned lp;
    asm("cvt.rn.bf16x2.f32 %0, %1, %2;" : "=r"(lp) : "f"(l1), "f"(l0));
    hi = h; lo = lp;
}

__device__ __forceinline__ void mma_bf16(float* c,
    unsigned a0, unsigned a1, unsigned a2, unsigned a3, unsigned b0, unsigned b1)
{
    asm("mma.sync.aligned.m16n8k16.row.col.f32.bf16.bf16.f32 "
        "{%0,%1,%2,%3}, {%4,%5,%6,%7}, {%8,%9}, {%0,%1,%2,%3};"
        : "+f"(c[0]), "+f"(c[1]), "+f"(c[2]), "+f"(c[3])
        : "r"(a0), "r"(a1), "r"(a2), "r"(a3), "r"(b0), "r"(b1));
}

// ---------------------------------------------------------------------------
// GEMM NT via tensor cores: out[i][o] = sum_h A[i][h]*W[o][h] + bias[o]
// CTA tile 64(M) x 32(N), BK=16, 128 threads (4 warps, warp tile 32x16).
// A/W staged in smem PRE-SPLIT into packed-bf16x2 hi/lo planes, pad 12
// (bank-conflict-free for all fragment LDS.32 patterns). Double buffered.
// ---------------------------------------------------------------------------
__device__ __forceinline__ void gemm_body(
    const float* __restrict__ A, const float* __restrict__ W,
    const float* __restrict__ bias, float* __restrict__ out)
{
    __shared__ unsigned Ah[2][64][12], Al[2][64][12];
    __shared__ unsigned Bh[2][32][12], Bl[2][32][12];

    int t = threadIdx.x;
    int row0 = blockIdx.y * 64, col0 = blockIdx.x * 32;
    int lane = t & 31, warp = t >> 5;
    int wm = warp >> 1, wn = warp & 1;     // warp grid 2x2 over 64x32
    int g = lane >> 2, tq = lane & 3;

    int lrA = t >> 1, hA = t & 1;          // A loader: row 0..63, k-half
    int lrB = t >> 2, qB = t & 3;          // B loader: row 0..31, k-quarter

    const float* Ap = A + (row0 + lrA) * HIDDEN + hA * 8;
    const float* Bp = W + (col0 + lrB) * HIDDEN + qB * 4;

    float acc[2][2][4];
#pragma unroll
    for (int mt = 0; mt < 2; mt++)
#pragma unroll
        for (int nt = 0; nt < 2; nt++)
#pragma unroll
            for (int x = 0; x < 4; x++) acc[mt][nt][x] = 0.0f;

    float4 af0 = *(const float4*)(Ap);
    float4 af1 = *(const float4*)(Ap + 4);
    float4 bf  = *(const float4*)(Bp);

    // split + store block 0
    {
        unsigned h0, l0, h1, l1, h2, l2, h3, l3;
        split2(af0.x, af0.y, h0, l0); split2(af0.z, af0.w, h1, l1);
        split2(af1.x, af1.y, h2, l2); split2(af1.z, af1.w, h3, l3);
        *(uint4*)&Ah[0][lrA][hA * 4] = make_uint4(h0, h1, h2, h3);
        *(uint4*)&Al[0][lrA][hA * 4] = make_uint4(l0, l1, l2, l3);
        unsigned bh0, bl0, bh1, bl1;
        split2(bf.x, bf.y, bh0, bl0); split2(bf.z, bf.w, bh1, bl1);
        *(uint2*)&Bh[0][lrB][qB * 2] = make_uint2(bh0, bh1);
        *(uint2*)&Bl[0][lrB][qB * 2] = make_uint2(bl0, bl1);
    }
    __syncthreads();

    int buf = 0;
#pragma unroll 1
    for (int kb = 0; kb < 32; kb++) {
        if (kb < 31) {
            af0 = *(const float4*)(Ap + (kb + 1) * 16);
            af1 = *(const float4*)(Ap + (kb + 1) * 16 + 4);
            bf  = *(const float4*)(Bp + (kb + 1) * 16);
        }
        // compute from buf
        unsigned ah[2][4], al[2][4];
#pragma unroll
        for (int mt = 0; mt < 2; mt++) {
            int r = wm * 32 + mt * 16 + g;
            ah[mt][0] = Ah[buf][r][tq];         al[mt][0] = Al[buf][r][tq];
            ah[mt][1] = Ah[buf][r + 8][tq];     al[mt][1] = Al[buf][r + 8][tq];
            ah[mt][2] = Ah[buf][r][tq + 4];     al[mt][2] = Al[buf][r][tq + 4];
            ah[mt][3] = Ah[buf][r + 8][tq + 4]; al[mt][3] = Al[buf][r + 8][tq + 4];
        }
#pragma unroll
        for (int nt = 0; nt < 2; nt++) {
            int n = wn * 16 + nt * 8 + g;
            unsigned bh0 = Bh[buf][n][tq], bh1 = Bh[buf][n][tq + 4];
            unsigned bl0 = Bl[buf][n][tq], bl1 = Bl[buf][n][tq + 4];
#pragma unroll
            for (int mt = 0; mt < 2; mt++) {
                mma_bf16(acc[mt][nt], ah[mt][0], ah[mt][1], ah[mt][2], ah[mt][3], bh0, bh1);
                mma_bf16(acc[mt][nt], ah[mt][0], ah[mt][1], ah[mt][2], ah[mt][3], bl0, bl1);
                mma_bf16(acc[mt][nt], al[mt][0], al[mt][1], al[mt][2], al[mt][3], bh0, bh1);
            }
        }
        if (kb < 31) {
            int nb = buf ^ 1;
            unsigned h0, l0, h1, l1, h2, l2, h3, l3;
            split2(af0.x, af0.y, h0, l0); split2(af0.z, af0.w, h1, l1);
            split2(af1.x, af1.y, h2, l2); split2(af1.z, af1.w, h3, l3);
            *(uint4*)&Ah[nb][lrA][hA * 4] = make_uint4(h0, h1, h2, h3);
            *(uint4*)&Al[nb][lrA][hA * 4] = make_uint4(l0, l1, l2, l3);
            unsigned bh0, bl0, bh1, bl1;
            split2(bf.x, bf.y, bh0, bl0); split2(bf.z, bf.w, bh1, bl1);
            *(uint2*)&Bh[nb][lrB][qB * 2] = make_uint2(bh0, bh1);
            *(uint2*)&Bl[nb][lrB][qB * 2] = make_uint2(bl0, bl1);
            __syncthreads();
            buf = nb;
        }
    }

    // epilogue: c0 (g, 2t), c1 (g, 2t+1), c2 (g+8, 2t), c3 (g+8, 2t+1)
#pragma unroll
    for (int mt = 0; mt < 2; mt++) {
#pragma unroll
        for (int nt = 0; nt < 2; nt++) {
            int row = row0 + wm * 32 + mt * 16 + g;
            int col = col0 + wn * 16 + nt * 8 + 2 * tq;
            float2 b2 = *(const float2*)(bias + col);
            float* c = acc[mt][nt];
            *(float2*)(out + row * HIDDEN + col) =
                make_float2(c[0] + b2.x, c[1] + b2.y);
            *(float2*)(out + (row + 8) * HIDDEN + col) =
                make_float2(c[2] + b2.x, c[3] + b2.y);
        }
    }
}

__global__ __launch_bounds__(128) void qkv_mma_kernel(
    const float* __restrict__ X,
    const float* __restrict__ Wq, const float* __restrict__ bq,
    const float* __restrict__ Wk, const float* __restrict__ bk,
    const float* __restrict__ Wv, const float* __restrict__ bv)
{
    if (blockIdx.z == 0)      gemm_body(X, Wq, bq, g_q);
    else if (blockIdx.z == 1) gemm_body(X, Wk, bk, g_k);
    else                      gemm_body(X, Wv, bv, g_v);
}

__global__ __launch_bounds__(128) void out_mma_kernel(
    const float* __restrict__ Wo, const float* __restrict__ bo,
    float* __restrict__ out)
{
    gemm_body(g_ctxsum, Wo, bo, out);
}

// ---------------------------------------------------------------------------
// Inhibitor: CTA = (i-tile of 32, head, j-split of 64), 128 threads.
//   z[i,j] = coef*(|q_i|^2 + |k_j|^2 - 2 q.k) + zc + (1-mask[j])*1e10
//   ctx[i,k] = sum_j max(v[j,k], z[i,j]) - sum_j z[i,j]      (relu trick)
// ---------------------------------------------------------------------------
__global__ __launch_bounds__(128) void inhib_kernel(const float* __restrict__ mask,
                                                    const float* __restrict__ gamma)
{
    __shared__ float qs[64][36];     // [d][i]  transposed q tile (i: 32)
    __shared__ float ks[32][72];     // [j][d]
    __shared__ float vs[32][72];     // [j][k]
    __shared__ float zs[32][33];     // [i][j]
    __shared__ float q2s[32];        // coef * |q_i|^2
    __shared__ float kps[32][4];     // |k_j|^2 partials
    __shared__ float ms[64];         // (1-mask)*1e10 for this CTA's 64 j's

    int t = threadIdx.x;
    int i0 = blockIdx.x * 32, head = blockIdx.y, js = blockIdx.z;

    float g = gamma[0];
    float gsd = g * 8.0f;                 // g * sqrt(D), D=64
    float coef = 15.0f / (16.0f * gsd);
    float zc = 12.0f / gsd;               // (3*D/16) / (g*sqrt(D))
    float m2c = -2.0f * coef;

    // load q tile transposed: thread (lr=row 0..31, lc=d-quarter)
    {
        int lr = t >> 2, lc = t & 3;
#pragma unroll
        for (int c = 0; c < 4; c++) {
            float4 f = *(const float4*)(g_q + (i0 + lr) * HIDDEN + head * HD + lc * 16 + c * 4);
            int d = lc * 16 + c * 4;
            qs[d + 0][lr] = f.x; qs[d + 1][lr] = f.y;
            qs[d + 2][lr] = f.z; qs[d + 3][lr] = f.w;
        }
    }
    if (t < 64) ms[t] = (1.0f - mask[js * 64 + t]) * 1e10f;
    __syncthreads();
    if (t < 32) {
        float s = 0.0f;
#pragma unroll 8
        for (int d = 0; d < 64; d++) { float q = qs[d][t]; s = fmaf(q, q, s); }
        q2s[t] = coef * s;
    }

    // prefetch chunk 0 of k/v: thread (jrow 0..31, lc d-quarter)
    int jrow = t >> 2, lc2 = t & 3;
    const float* kp = g_k + (js * 64 + jrow) * HIDDEN + head * HD + lc2 * 16;
    const float* vp = g_v + (js * 64 + jrow) * HIDDEN + head * HD + lc2 * 16;
    float4 kf[4], vf[4];
#pragma unroll
    for (int c = 0; c < 4; c++) { kf[c] = *(const float4*)(kp + c * 4);
                                  vf[c] = *(const float4*)(vp + c * 4); }

    float acc[16];
#pragma unroll
    for (int x = 0; x < 16; x++) acc[x] = 0.0f;
    float accz = 0.0f;

    int il = t & 31, kq = t >> 5;    // acc mapping: i-local (0..31), k-quarter
    int ti = t & 7, tj = t >> 3;     // z mapping: i-group (0..7), j-pair (0..15)

#pragma unroll 1
    for (int c = 0; c < 2; c++) {
        __syncthreads();  // all reads of ks/vs/zs from previous chunk done
        float kp2 = 0.0f;
#pragma unroll
        for (int cc = 0; cc < 4; cc++) {
            *(float4*)&ks[jrow][lc2 * 16 + cc * 4] = kf[cc];
            kp2 = fmaf(kf[cc].x, kf[cc].x, kp2);
            kp2 = fmaf(kf[cc].y, kf[cc].y, kp2);
            kp2 = fmaf(kf[cc].z, kf[cc].z, kp2);
            kp2 = fmaf(kf[cc].w, kf[cc].w, kp2);
            *(float4*)&vs[jrow][lc2 * 16 + cc * 4] = vf[cc];
        }
        kps[jrow][lc2] = kp2;
        if (c < 1) {  // prefetch next chunk
#pragma unroll
            for (int cc = 0; cc < 4; cc++) {
                kf[cc] = *(const float4*)(kp + 32 * HIDDEN + cc * 4);
                vf[cc] = *(const float4*)(vp + 32 * HIDDEN + cc * 4);
            }
        }
        __syncthreads();

        // z phase: 4 i's x 2 j's per thread
        {
            float dot[4][2];
#pragma unroll
            for (int a = 0; a < 4; a++) { dot[a][0] = 0.0f; dot[a][1] = 0.0f; }
#pragma unroll 8
            for (int d = 0; d < 64; d++) {
                float4 a4 = *(const float4*)&qs[d][ti * 4];
                float k0 = ks[tj * 2 + 0][d];
                float k1 = ks[tj * 2 + 1][d];
                dot[0][0] = fmaf(a4.x, k0, dot[0][0]);
                dot[0][1] = fmaf(a4.x, k1, dot[0][1]);
                dot[1][0] = fmaf(a4.y, k0, dot[1][0]);
                dot[1][1] = fmaf(a4.y, k1, dot[1][1]);
                dot[2][0] = fmaf(a4.z, k0, dot[2][0]);
                dot[2][1] = fmaf(a4.z, k1, dot[2][1]);
                dot[3][0] = fmaf(a4.w, k0, dot[3][0]);
                dot[3][1] = fmaf(a4.w, k1, dot[3][1]);
            }
            int j0 = tj * 2, j1 = tj * 2 + 1;
            float kt0 = fmaf(coef, kps[j0][0] + kps[j0][1] + kps[j0][2] + kps[j0][3],
                             zc + ms[c * 32 + j0]);
            float kt1 = fmaf(coef, kps[j1][0] + kps[j1][1] + kps[j1][2] + kps[j1][3],
                             zc + ms[c * 32 + j1]);
#pragma unroll
            for (int mi = 0; mi < 4; mi++) {
                float qt = q2s[ti * 4 + mi];
                zs[ti * 4 + mi][j0] = fmaf(m2c, dot[mi][0], qt + kt0);
                zs[ti * 4 + mi][j1] = fmaf(m2c, dot[mi][1], qt + kt1);
            }
        }
        __syncthreads();

        // accumulation: ctx += max(v, z); accz += z
#pragma unroll 4
        for (int jj = 0; jj < 32; jj++) {
            float z = zs[il][jj];
            accz += z;
#pragma unroll
            for (int cc = 0; cc < 4; cc++) {
                float4 v4 = *(const float4*)&vs[jj][kq * 16 + cc * 4];
                acc[cc * 4 + 0] += fmaxf(v4.x, z);
                acc[cc * 4 + 1] += fmaxf(v4.y, z);
                acc[cc * 4 + 2] += fmaxf(v4.z, z);
                acc[cc * 4 + 3] += fmaxf(v4.w, z);
            }
        }
    }

    float* outp = g_ctx[js] + (i0 + il) * HIDDEN + head * HD + kq * 16;
#pragma unroll
    for (int cc = 0; cc < 4; cc++) {
        *(float4*)(outp + cc * 4) = make_float4(acc[cc * 4 + 0] - accz,
                                                acc[cc * 4 + 1] - accz,
                                                acc[cc * 4 + 2] - accz,
                                                acc[cc * 4 + 3] - accz);
    }
}

// ---------------------------------------------------------------------------
// Reduce 8 ctx partials -> g_ctxsum
// ---------------------------------------------------------------------------
__global__ __launch_bounds__(256) void reduce_kernel()
{
    int idx = (blockIdx.x * 256 + threadIdx.x) * 4;
    float4 s = make_float4(0.0f, 0.0f, 0.0f, 0.0f);
#pragma unroll
    for (int p = 0; p < NPART; p++) {
        float4 v = *(const float4*)&g_ctx[p][idx];
        s.x += v.x; s.y += v.y; s.z += v.z; s.w += v.w;
    }
    *(float4*)&g_ctxsum[idx] = s;
}

extern "C" void kernel_launch(void* const* d_in, const int* in_sizes, int n_in,
                              void* d_out, int out_size)
{
    const float* X     = (const float*)d_in[0];
    const float* mask  = (const float*)d_in[1];
    const float* Wq    = (const float*)d_in[2];
    const float* bq    = (const float*)d_in[3];
    const float* Wk    = (const float*)d_in[4];
    const float* bk    = (const float*)d_in[5];
    const float* Wv    = (const float*)d_in[6];
    const float* bv    = (const float*)d_in[7];
    const float* Wo    = (const float*)d_in[8];
    const float* bo    = (const float*)d_in[9];
    const float* gamma = (const float*)d_in[10];
    float* out = (float*)d_out;

    qkv_mma_kernel<<<dim3(16, 8, 3), 128>>>(X, Wq, bq, Wk, bk, Wv, bv);
    inhib_kernel<<<dim3(16, 8, NPART), 128>>>(mask, gamma);
    reduce_kernel<<<256, 256>>>();
    out_mma_kernel<<<dim3(16, 8), 128>>>(Wo, bo, out);
}

// round 5
// speedup vs baseline: 1.5479x; 1.0034x over previous
#include <cuda_runtime.h>

#define SEQ 512
#define HIDDEN 512
#define HD 64
#define NPART 8

// Scratch (static __device__, no allocation)
__device__ float g_q[SEQ * HIDDEN];
__device__ float g_k[SEQ * HIDDEN];
__device__ float g_v[SEQ * HIDDEN];
__device__ float g_ctx[NPART][SEQ * HIDDEN];
__device__ float g_ctxsum[SEQ * HIDDEN];

// ---------------------------------------------------------------------------
// bf16x3 split helpers.
// ---------------------------------------------------------------------------
__device__ __forceinline__ void split2(float x0, float x1, unsigned& hi, unsigned& lo)
{
    unsigned u0 = __float_as_uint(x0), u1 = __float_as_uint(x1);
    unsigned h;
    asm("prmt.b32 %0, %1, %2, 0x7632;" : "=r"(h) : "r"(u0), "r"(u1));
    float l0 = x0 - __uint_as_float(u0 & 0xFFFF0000u);
    float l1 = x1 - __uint_as_float(u1 & 0xFFFF0000u);
    unsigned lp;
    asm("cvt.rn.bf16x2.f32 %0, %1, %2;" : "=r"(lp) : "f"(l1), "f"(l0));
    hi = h; lo = lp;
}

__device__ __forceinline__ void mma_bf16(float* c,
    unsigned a0, unsigned a1, unsigned a2, unsigned a3, unsigned b0, unsigned b1)
{
    asm("mma.sync.aligned.m16n8k16.row.col.f32.bf16.bf16.f32 "
        "{%0,%1,%2,%3}, {%4,%5,%6,%7}, {%8,%9}, {%0,%1,%2,%3};"
        : "+f"(c[0]), "+f"(c[1]), "+f"(c[2]), "+f"(c[3])
        : "r"(a0), "r"(a1), "r"(a2), "r"(a3), "r"(b0), "r"(b1));
}

// ---------------------------------------------------------------------------
// GEMM NT via tensor cores: out[i][o] = sum_h A[i][h]*W[o][h] + bias[o]
// CTA tile 32(M) x 32(N), BK=16, 128 threads (4 warps, warp grid 2x2,
// warp tile 16x16). Pre-split bf16x2 hi/lo planes in smem, pad 12,
// double buffered. More CTAs + shorter chains = latency actually hidden.
// ---------------------------------------------------------------------------
__device__ __forceinline__ void gemm_body(
    const float* __restrict__ A, const float* __restrict__ W,
    const float* __restrict__ bias, float* __restrict__ out)
{
    __shared__ unsigned Ah[2][32][12], Al[2][32][12];
    __shared__ unsigned Bh[2][32][12], Bl[2][32][12];

    int t = threadIdx.x;
    int row0 = blockIdx.y * 32, col0 = blockIdx.x * 32;
    int lane = t & 31, warp = t >> 5;
    int wm = warp >> 1, wn = warp & 1;     // warp grid 2x2 over 32x32
    int g = lane >> 2, tq = lane & 3;

    int lr = t >> 2, q = t & 3;            // loader: row 0..31, k-quarter

    const float* Ap = A + (row0 + lr) * HIDDEN + q * 4;
    const float* Bp = W + (col0 + lr) * HIDDEN + q * 4;

    float acc[2][4];
#pragma unroll
    for (int nt = 0; nt < 2; nt++)
#pragma unroll
        for (int x = 0; x < 4; x++) acc[nt][x] = 0.0f;

    float4 af = *(const float4*)(Ap);
    float4 bf = *(const float4*)(Bp);

    {
        unsigned h0, l0, h1, l1;
        split2(af.x, af.y, h0, l0); split2(af.z, af.w, h1, l1);
        *(uint2*)&Ah[0][lr][q * 2] = make_uint2(h0, h1);
        *(uint2*)&Al[0][lr][q * 2] = make_uint2(l0, l1);
        split2(bf.x, bf.y, h0, l0); split2(bf.z, bf.w, h1, l1);
        *(uint2*)&Bh[0][lr][q * 2] = make_uint2(h0, h1);
        *(uint2*)&Bl[0][lr][q * 2] = make_uint2(l0, l1);
    }
    __syncthreads();

    int buf = 0;
#pragma unroll 1
    for (int kb = 0; kb < 32; kb++) {
        if (kb < 31) {
            af = *(const float4*)(Ap + (kb + 1) * 16);
            bf = *(const float4*)(Bp + (kb + 1) * 16);
        }
        int r = wm * 16 + g;
        unsigned ah0 = Ah[buf][r][tq],     ah1 = Ah[buf][r + 8][tq];
        unsigned ah2 = Ah[buf][r][tq + 4], ah3 = Ah[buf][r + 8][tq + 4];
        unsigned al0 = Al[buf][r][tq],     al1 = Al[buf][r + 8][tq];
        unsigned al2 = Al[buf][r][tq + 4], al3 = Al[buf][r + 8][tq + 4];
#pragma unroll
        for (int nt = 0; nt < 2; nt++) {
            int n = wn * 16 + nt * 8 + g;
            unsigned bh0 = Bh[buf][n][tq], bh1 = Bh[buf][n][tq + 4];
            unsigned bl0 = Bl[buf][n][tq], bl1 = Bl[buf][n][tq + 4];
            mma_bf16(acc[nt], ah0, ah1, ah2, ah3, bh0, bh1);
            mma_bf16(acc[nt], ah0, ah1, ah2, ah3, bl0, bl1);
            mma_bf16(acc[nt], al0, al1, al2, al3, bh0, bh1);
        }
        if (kb < 31) {
            int nb = buf ^ 1;
            unsigned h0, l0, h1, l1;
            split2(af.x, af.y, h0, l0); split2(af.z, af.w, h1, l1);
            *(uint2*)&Ah[nb][lr][q * 2] = make_uint2(h0, h1);
            *(uint2*)&Al[nb][lr][q * 2] = make_uint2(l0, l1);
            split2(bf.x, bf.y, h0, l0); split2(bf.z, bf.w, h1, l1);
            *(uint2*)&Bh[nb][lr][q * 2] = make_uint2(h0, h1);
            *(uint2*)&Bl[nb][lr][q * 2] = make_uint2(l0, l1);
            __syncthreads();
            buf = nb;
        }
    }

#pragma unroll
    for (int nt = 0; nt < 2; nt++) {
        int row = row0 + wm * 16 + g;
        int col = col0 + wn * 16 + nt * 8 + 2 * tq;
        float2 b2 = *(const float2*)(bias + col);
        float* c = acc[nt];
        *(float2*)(out + row * HIDDEN + col) = make_float2(c[0] + b2.x, c[1] + b2.y);
        *(float2*)(out + (row + 8) * HIDDEN + col) = make_float2(c[2] + b2.x, c[3] + b2.y);
    }
}

__global__ __launch_bounds__(128) void qkv_mma_kernel(
    const float* __restrict__ X,
    const float* __restrict__ Wq, const float* __restrict__ bq,
    const float* __restrict__ Wk, const float* __restrict__ bk,
    const float* __restrict__ Wv, const float* __restrict__ bv)
{
    if (blockIdx.z == 0)      gemm_body(X, Wq, bq, g_q);
    else if (blockIdx.z == 1) gemm_body(X, Wk, bk, g_k);
    else                      gemm_body(X, Wv, bv, g_v);
}

__global__ __launch_bounds__(128) void out_mma_kernel(
    const float* __restrict__ Wo, const float* __restrict__ bo,
    float* __restrict__ out)
{
    gemm_body(g_ctxsum, Wo, bo, out);
}

// ---------------------------------------------------------------------------
// Inhibitor: CTA = (i-tile of 32, head, j-split of 64), 128 threads.
//   ctx[i,k] = sum_j max(v[j,k], z[i,j]) - sum_j z[i,j]      (relu trick)
// ---------------------------------------------------------------------------
__global__ __launch_bounds__(128) void inhib_kernel(const float* __restrict__ mask,
                                                    const float* __restrict__ gamma)
{
    __shared__ float qs[64][36];
    __shared__ float ks[32][72];
    __shared__ float vs[32][72];
    __shared__ float zs[32][33];
    __shared__ float q2s[32];
    __shared__ float kps[32][4];
    __shared__ float ms[64];

    int t = threadIdx.x;
    int i0 = blockIdx.x * 32, head = blockIdx.y, js = blockIdx.z;

    float g = gamma[0];
    float gsd = g * 8.0f;
    float coef = 15.0f / (16.0f * gsd);
    float zc = 12.0f / gsd;
    float m2c = -2.0f * coef;

    {
        int lr = t >> 2, lc = t & 3;
#pragma unroll
        for (int c = 0; c < 4; c++) {
            float4 f = *(const float4*)(g_q + (i0 + lr) * HIDDEN + head * HD + lc * 16 + c * 4);
            int d = lc * 16 + c * 4;
            qs[d + 0][lr] = f.x; qs[d + 1][lr] = f.y;
            qs[d + 2][lr] = f.z; qs[d + 3][lr] = f.w;
        }
    }
    if (t < 64) ms[t] = (1.0f - mask[js * 64 + t]) * 1e10f;
    __syncthreads();
    if (t < 32) {
        float s = 0.0f;
#pragma unroll 8
        for (int d = 0; d < 64; d++) { float qv = qs[d][t]; s = fmaf(qv, qv, s); }
        q2s[t] = coef * s;
    }

    int jrow = t >> 2, lc2 = t & 3;
    const float* kp = g_k + (js * 64 + jrow) * HIDDEN + head * HD + lc2 * 16;
    const float* vp = g_v + (js * 64 + jrow) * HIDDEN + head * HD + lc2 * 16;
    float4 kf[4], vf[4];
#pragma unroll
    for (int c = 0; c < 4; c++) { kf[c] = *(const float4*)(kp + c * 4);
                                  vf[c] = *(const float4*)(vp + c * 4); }

    float acc[16];
#pragma unroll
    for (int x = 0; x < 16; x++) acc[x] = 0.0f;
    float accz = 0.0f;

    int il = t & 31, kq = t >> 5;
    int ti = t & 7, tj = t >> 3;

#pragma unroll 1
    for (int c = 0; c < 2; c++) {
        __syncthreads();
        float kp2 = 0.0f;
#pragma unroll
        for (int cc = 0; cc < 4; cc++) {
            *(float4*)&ks[jrow][lc2 * 16 + cc * 4] = kf[cc];
            kp2 = fmaf(kf[cc].x, kf[cc].x, kp2);
            kp2 = fmaf(kf[cc].y, kf[cc].y, kp2);
            kp2 = fmaf(kf[cc].z, kf[cc].z, kp2);
            kp2 = fmaf(kf[cc].w, kf[cc].w, kp2);
            *(float4*)&vs[jrow][lc2 * 16 + cc * 4] = vf[cc];
        }
        kps[jrow][lc2] = kp2;
        if (c < 1) {
#pragma unroll
            for (int cc = 0; cc < 4; cc++) {
                kf[cc] = *(const float4*)(kp + 32 * HIDDEN + cc * 4);
                vf[cc] = *(const float4*)(vp + 32 * HIDDEN + cc * 4);
            }
        }
        __syncthreads();

        {
            float dot[4][2];
#pragma unroll
            for (int a = 0; a < 4; a++) { dot[a][0] = 0.0f; dot[a][1] = 0.0f; }
#pragma unroll 8
            for (int d = 0; d < 64; d++) {
                float4 a4 = *(const float4*)&qs[d][ti * 4];
                float k0 = ks[tj * 2 + 0][d];
                float k1 = ks[tj * 2 + 1][d];
                dot[0][0] = fmaf(a4.x, k0, dot[0][0]);
                dot[0][1] = fmaf(a4.x, k1, dot[0][1]);
                dot[1][0] = fmaf(a4.y, k0, dot[1][0]);
                dot[1][1] = fmaf(a4.y, k1, dot[1][1]);
                dot[2][0] = fmaf(a4.z, k0, dot[2][0]);
                dot[2][1] = fmaf(a4.z, k1, dot[2][1]);
                dot[3][0] = fmaf(a4.w, k0, dot[3][0]);
                dot[3][1] = fmaf(a4.w, k1, dot[3][1]);
            }
            int j0 = tj * 2, j1 = tj * 2 + 1;
            float kt0 = fmaf(coef, kps[j0][0] + kps[j0][1] + kps[j0][2] + kps[j0][3],
                             zc + ms[c * 32 + j0]);
            float kt1 = fmaf(coef, kps[j1][0] + kps[j1][1] + kps[j1][2] + kps[j1][3],
                             zc + ms[c * 32 + j1]);
#pragma unroll
            for (int mi = 0; mi < 4; mi++) {
                float qt = q2s[ti * 4 + mi];
                zs[ti * 4 + mi][j0] = fmaf(m2c, dot[mi][0], qt + kt0);
                zs[ti * 4 + mi][j1] = fmaf(m2c, dot[mi][1], qt + kt1);
            }
        }
        __syncthreads();

#pragma unroll 4
        for (int jj = 0; jj < 32; jj++) {
            float z = zs[il][jj];
            accz += z;
#pragma unroll
            for (int cc = 0; cc < 4; cc++) {
                float4 v4 = *(const float4*)&vs[jj][kq * 16 + cc * 4];
                acc[cc * 4 + 0] += fmaxf(v4.x, z);
                acc[cc * 4 + 1] += fmaxf(v4.y, z);
                acc[cc * 4 + 2] += fmaxf(v4.z, z);
                acc[cc * 4 + 3] += fmaxf(v4.w, z);
            }
        }
    }

    float* outp = g_ctx[js] + (i0 + il) * HIDDEN + head * HD + kq * 16;
#pragma unroll
    for (int cc = 0; cc < 4; cc++) {
        *(float4*)(outp + cc * 4) = make_float4(acc[cc * 4 + 0] - accz,
                                                acc[cc * 4 + 1] - accz,
                                                acc[cc * 4 + 2] - accz,
                                                acc[cc * 4 + 3] - accz);
    }
}

// ---------------------------------------------------------------------------
// Reduce 8 ctx partials -> g_ctxsum
// ---------------------------------------------------------------------------
__global__ __launch_bounds__(256) void reduce_kernel()
{
    int idx = (blockIdx.x * 256 + threadIdx.x) * 4;
    float4 s = make_float4(0.0f, 0.0f, 0.0f, 0.0f);
#pragma unroll
    for (int p = 0; p < NPART; p++) {
        float4 v = *(const float4*)&g_ctx[p][idx];
        s.x += v.x; s.y += v.y; s.z += v.z; s.w += v.w;
    }
    *(float4*)&g_ctxsum[idx] = s;
}

extern "C" void kernel_launch(void* const* d_in, const int* in_sizes, int n_in,
                              void* d_out, int out_size)
{
    const float* X     = (const float*)d_in[0];
    const float* mask  = (const float*)d_in[1];
    const float* Wq    = (const float*)d_in[2];
    const float* bq    = (const float*)d_in[3];
    const float* Wk    = (const float*)d_in[4];
    const float* bk    = (const float*)d_in[5];
    const float* Wv    = (const float*)d_in[6];
    const float* bv    = (const float*)d_in[7];
    const float* Wo    = (const float*)d_in[8];
    const float* bo    = (const float*)d_in[9];
    const float* gamma = (const float*)d_in[10];
    float* out = (float*)d_out;

    qkv_mma_kernel<<<dim3(16, 16, 3), 128>>>(X, Wq, bq, Wk, bk, Wv, bv);
    inhib_kernel<<<dim3(16, 8, NPART), 128>>>(mask, gamma);
    reduce_kernel<<<256, 256>>>();
    out_mma_kernel<<<dim3(16, 16), 128>>>(Wo, bo, out);
}

// round 6
// speedup vs baseline: 1.7535x; 1.1328x over previous
#include <cuda_runtime.h>

#define SEQ 512
#define HIDDEN 512
#define HD 64
#define NPART 8

// ---------------------------------------------------------------------------
// Scratch (static __device__, no allocation)
// ---------------------------------------------------------------------------
__device__ unsigned g_Xh[SEQ * 256], g_Xl[SEQ * 256];
__device__ unsigned g_Wqh[SEQ * 256], g_Wql[SEQ * 256];
__device__ unsigned g_Wkh[SEQ * 256], g_Wkl[SEQ * 256];
__device__ unsigned g_Wvh[SEQ * 256], g_Wvl[SEQ * 256];
__device__ unsigned g_Woh[SEQ * 256], g_Wol[SEQ * 256];
__device__ float    g_q[SEQ * HIDDEN], g_k[SEQ * HIDDEN], g_v[SEQ * HIDDEN];
__device__ unsigned g_qh[SEQ * 256], g_ql[SEQ * 256];
__device__ unsigned g_kh[SEQ * 256], g_kl[SEQ * 256];
__device__ float    g_zq[8 * SEQ], g_zkm[8 * SEQ];
__device__ float    g_z[8 * SEQ * SEQ];
__device__ float    g_ctx[NPART][SEQ * HIDDEN];
__device__ unsigned g_Ch[SEQ * 256], g_Cl[SEQ * 256];

// ---------------------------------------------------------------------------
// bf16x3 split: hi = exact top-16 truncation, lo = rn_bf16(x - hi).
// Packed u32: low 16 bits = element with SMALLER k.
// ---------------------------------------------------------------------------
__device__ __forceinline__ void split2(float x0, float x1, unsigned& hi, unsigned& lo)
{
    unsigned u0 = __float_as_uint(x0), u1 = __float_as_uint(x1);
    unsigned h;
    asm("prmt.b32 %0, %1, %2, 0x7632;" : "=r"(h) : "r"(u0), "r"(u1));
    float l0 = x0 - __uint_as_float(u0 & 0xFFFF0000u);
    float l1 = x1 - __uint_as_float(u1 & 0xFFFF0000u);
    unsigned lp;
    asm("cvt.rn.bf16x2.f32 %0, %1, %2;" : "=r"(lp) : "f"(l1), "f"(l0));
    hi = h; lo = lp;
}

__device__ __forceinline__ void mma_bf16(float* c,
    unsigned a0, unsigned a1, unsigned a2, unsigned a3, unsigned b0, unsigned b1)
{
    asm("mma.sync.aligned.m16n8k16.row.col.f32.bf16.bf16.f32 "
        "{%0,%1,%2,%3}, {%4,%5,%6,%7}, {%8,%9}, {%0,%1,%2,%3};"
        : "+f"(c[0]), "+f"(c[1]), "+f"(c[2]), "+f"(c[3])
        : "r"(a0), "r"(a1), "r"(a2), "r"(a3), "r"(b0), "r"(b1));
}

__device__ __forceinline__ void cp16(void* dst, const void* src)
{
    unsigned d = (unsigned)__cvta_generic_to_shared(dst);
    asm volatile("cp.async.cg.shared.global [%0], [%1], 16;" :: "r"(d), "l"(src));
}
#define CP_COMMIT() asm volatile("cp.async.commit_group;")

// ---------------------------------------------------------------------------
// Convert: split 5 f32 matrices into packed hi/lo planes. grid (512,1,5)x256.
// ---------------------------------------------------------------------------
__global__ __launch_bounds__(256) void convert_kernel(
    const float* __restrict__ X, const float* __restrict__ Wq,
    const float* __restrict__ Wk, const float* __restrict__ Wv,
    const float* __restrict__ Wo)
{
    const float* src; unsigned* dh; unsigned* dl;
    switch (blockIdx.z) {
        case 0:  src = X;  dh = g_Xh;  dl = g_Xl;  break;
        case 1:  src = Wq; dh = g_Wqh; dl = g_Wql; break;
        case 2:  src = Wk; dh = g_Wkh; dl = g_Wkl; break;
        case 3:  src = Wv; dh = g_Wvh; dl = g_Wvl; break;
        default: src = Wo; dh = g_Woh; dl = g_Wol; break;
    }
    int idx = blockIdx.x * 256 + threadIdx.x;
    float2 v = *(const float2*)(src + idx * 2);
    unsigned h, l; split2(v.x, v.y, h, l);
    dh[idx] = h; dl[idx] = l;
}

// ---------------------------------------------------------------------------
// GEMM NT on pre-split planes: out[i][o] = sum_h A[i][h]*W[o][h] + bias[o]
// CTA tile 32(M) x 64(N), BK=16, 128 threads (4 warps 2x2, warp tile 16x32),
// cp.async 4-stage pipeline, pad-12 rows (bank-conflict-free fragments).
// Optionally emits packed hi/lo planes of the (biased) result.
// ---------------------------------------------------------------------------
__device__ __forceinline__ void gemm_planes(
    const unsigned* __restrict__ Aph, const unsigned* __restrict__ Apl,
    const unsigned* __restrict__ Bph, const unsigned* __restrict__ Bpl,
    const float* __restrict__ bias, float* __restrict__ out,
    unsigned* __restrict__ outh, unsigned* __restrict__ outl)
{
    __shared__ unsigned smA[4][2][32][12];
    __shared__ unsigned smB[4][2][64][12];

    int t = threadIdx.x;
    int row0 = blockIdx.y * 32, col0 = blockIdx.x * 64;
    int lane = t & 31, warp = t >> 5;
    int wm = warp >> 1, wn = warp & 1;
    int g = lane >> 2, tq = lane & 3;

    int p = t >> 6;                 // plane (0=hi,1=lo), loader role
    int ar = (t >> 1) & 31, ahalf = t & 1;
    int br = t & 63;

    const unsigned* Asrc = (p ? Apl : Aph) + (row0 + ar) * 256 + ahalf * 4;
    const unsigned* Bsrc = (p ? Bpl : Bph) + (col0 + br) * 256;

    float acc[4][4];
#pragma unroll
    for (int nt = 0; nt < 4; nt++)
#pragma unroll
        for (int x = 0; x < 4; x++) acc[nt][x] = 0.0f;

#pragma unroll
    for (int s = 0; s < 3; s++) {
        cp16(&smA[s][p][ar][ahalf * 4], Asrc + s * 8);
        cp16(&smB[s][p][br][0], Bsrc + s * 8);
        cp16(&smB[s][p][br][4], Bsrc + s * 8 + 4);
        CP_COMMIT();
    }

#pragma unroll 1
    for (int kb = 0; kb < 32; kb++) {
        asm volatile("cp.async.wait_group 2;");
        __syncthreads();
        if (kb + 3 < 32) {
            int s = (kb + 3) & 3;
            cp16(&smA[s][p][ar][ahalf * 4], Asrc + (kb + 3) * 8);
            cp16(&smB[s][p][br][0], Bsrc + (kb + 3) * 8);
            cp16(&smB[s][p][br][4], Bsrc + (kb + 3) * 8 + 4);
        }
        CP_COMMIT();

        int st = kb & 3;
        int r = wm * 16 + g;
        unsigned ah0 = smA[st][0][r][tq],     ah1 = smA[st][0][r + 8][tq];
        unsigned ah2 = smA[st][0][r][tq + 4], ah3 = smA[st][0][r + 8][tq + 4];
        unsigned al0 = smA[st][1][r][tq],     al1 = smA[st][1][r + 8][tq];
        unsigned al2 = smA[st][1][r][tq + 4], al3 = smA[st][1][r + 8][tq + 4];
#pragma unroll
        for (int nt = 0; nt < 4; nt++) {
            int n = wn * 32 + nt * 8 + g;
            unsigned bh0 = smB[st][0][n][tq], bh1 = smB[st][0][n][tq + 4];
            unsigned bl0 = smB[st][1][n][tq], bl1 = smB[st][1][n][tq + 4];
            mma_bf16(acc[nt], ah0, ah1, ah2, ah3, bh0, bh1);
            mma_bf16(acc[nt], ah0, ah1, ah2, ah3, bl0, bl1);
            mma_bf16(acc[nt], al0, al1, al2, al3, bh0, bh1);
        }
    }
    asm volatile("cp.async.wait_group 0;");

#pragma unroll
    for (int nt = 0; nt < 4; nt++) {
        int row = row0 + wm * 16 + g;
        int col = col0 + wn * 32 + nt * 8 + 2 * tq;
        float2 b2 = *(const float2*)(bias + col);
        float v0 = acc[nt][0] + b2.x, v1 = acc[nt][1] + b2.y;
        float v2 = acc[nt][2] + b2.x, v3 = acc[nt][3] + b2.y;
        *(float2*)(out + row * HIDDEN + col) = make_float2(v0, v1);
        *(float2*)(out + (row + 8) * HIDDEN + col) = make_float2(v2, v3);
        if (outh) {
            unsigned h, l;
            split2(v0, v1, h, l);
            outh[row * 256 + (col >> 1)] = h; outl[row * 256 + (col >> 1)] = l;
            split2(v2, v3, h, l);
            outh[(row + 8) * 256 + (col >> 1)] = h; outl[(row + 8) * 256 + (col >> 1)] = l;
        }
    }
}

__global__ __launch_bounds__(128) void qkv_mma_kernel(
    const float* __restrict__ bq, const float* __restrict__ bk,
    const float* __restrict__ bv)
{
    if (blockIdx.z == 0)
        gemm_planes(g_Xh, g_Xl, g_Wqh, g_Wql, bq, g_q, g_qh, g_ql);
    else if (blockIdx.z == 1)
        gemm_planes(g_Xh, g_Xl, g_Wkh, g_Wkl, bk, g_k, g_kh, g_kl);
    else
        gemm_planes(g_Xh, g_Xl, g_Wvh, g_Wvl, bv, g_v, (unsigned*)0, (unsigned*)0);
}

__global__ __launch_bounds__(128) void out_mma_kernel(
    const float* __restrict__ bo, float* __restrict__ out)
{
    gemm_planes(g_Ch, g_Cl, g_Woh, g_Wol, bo, out, (unsigned*)0, (unsigned*)0);
}

// ---------------------------------------------------------------------------
// Norms: zq[h][i] = coef*|q|^2 ; zkm[h][j] = coef*|k|^2 + zc + (1-mask)*1e10
// 8192 tasks, grid 32x256.
// ---------------------------------------------------------------------------
__global__ __launch_bounds__(256) void norm_kernel(
    const float* __restrict__ mask, const float* __restrict__ gamma)
{
    int id = blockIdx.x * 256 + threadIdx.x;
    int which = id >> 12, head = (id >> 9) & 7, row = id & 511;
    const float* src = (which ? g_k : g_q) + row * HIDDEN + head * HD;
    float s = 0.0f;
#pragma unroll
    for (int c = 0; c < 16; c++) {
        float4 f = *(const float4*)(src + c * 4);
        s = fmaf(f.x, f.x, s); s = fmaf(f.y, f.y, s);
        s = fmaf(f.z, f.z, s); s = fmaf(f.w, f.w, s);
    }
    float gsd = gamma[0] * 8.0f;
    float coef = 15.0f / (16.0f * gsd);
    float zc = 12.0f / gsd;
    if (which)
        g_zkm[head * SEQ + row] = fmaf(coef, s, zc + (1.0f - mask[row]) * 1e10f);
    else
        g_zq[head * SEQ + row] = coef * s;
}

// ---------------------------------------------------------------------------
// z-kernel: per head, z[i][j] = m2c*(q_i . k_j) + zq[i] + zkm[j]
// CTA tile 64x64, K=64 (4 kb), one-shot cp.async load, 256 threads (8 warps,
// warp grid 4m x 2n, warp tile 16x32). grid (8,8,8).
// ---------------------------------------------------------------------------
__global__ __launch_bounds__(256) void z_kernel(const float* __restrict__ gamma)
{
    __shared__ unsigned smA[2][64][36];
    __shared__ unsigned smB[2][64][36];

    int t = threadIdx.x;
    int col0 = blockIdx.x * 64, row0 = blockIdx.y * 64, head = blockIdx.z;
    int lane = t & 31, warp = t >> 5;
    int wm = warp >> 1, wn = warp & 1;
    int g = lane >> 2, tq = lane & 3;

    int p = t >> 7, lrow = (t >> 1) & 63, half = t & 1;
    const unsigned* Asrc = (p ? g_ql : g_qh) + (row0 + lrow) * 256 + head * 32 + half * 16;
    const unsigned* Bsrc = (p ? g_kl : g_kh) + (col0 + lrow) * 256 + head * 32 + half * 16;
#pragma unroll
    for (int c = 0; c < 4; c++) {
        cp16(&smA[p][lrow][half * 16 + c * 4], Asrc + c * 4);
        cp16(&smB[p][lrow][half * 16 + c * 4], Bsrc + c * 4);
    }
    CP_COMMIT();
    asm volatile("cp.async.wait_group 0;");
    __syncthreads();

    float acc[4][4];
#pragma unroll
    for (int nt = 0; nt < 4; nt++)
#pragma unroll
        for (int x = 0; x < 4; x++) acc[nt][x] = 0.0f;

#pragma unroll
    for (int kb = 0; kb < 4; kb++) {
        int base = kb * 8;
        int r = wm * 16 + g;
        unsigned ah0 = smA[0][r][base + tq],     ah1 = smA[0][r + 8][base + tq];
        unsigned ah2 = smA[0][r][base + tq + 4], ah3 = smA[0][r + 8][base + tq + 4];
        unsigned al0 = smA[1][r][base + tq],     al1 = smA[1][r + 8][base + tq];
        unsigned al2 = smA[1][r][base + tq + 4], al3 = smA[1][r + 8][base + tq + 4];
#pragma unroll
        for (int nt = 0; nt < 4; nt++) {
            int n = wn * 32 + nt * 8 + g;
            unsigned bh0 = smB[0][n][base + tq], bh1 = smB[0][n][base + tq + 4];
            unsigned bl0 = smB[1][n][base + tq], bl1 = smB[1][n][base + tq + 4];
            mma_bf16(acc[nt], ah0, ah1, ah2, ah3, bh0, bh1);
            mma_bf16(acc[nt], ah0, ah1, ah2, ah3, bl0, bl1);
            mma_bf16(acc[nt], al0, al1, al2, al3, bh0, bh1);
        }
    }

    float gsd = gamma[0] * 8.0f;
    float m2c = -2.0f * 15.0f / (16.0f * gsd);
    int r = row0 + wm * 16 + g;
    float zq0 = g_zq[head * SEQ + r];
    float zq1 = g_zq[head * SEQ + r + 8];
    float* zbase = g_z + ((size_t)head * SEQ + r) * SEQ;
#pragma unroll
    for (int nt = 0; nt < 4; nt++) {
        int col = col0 + wn * 32 + nt * 8 + 2 * tq;
        float2 zk = *(const float2*)(g_zkm + head * SEQ + col);
        *(float2*)(zbase + col) =
            make_float2(fmaf(m2c, acc[nt][0], zq0 + zk.x),
                        fmaf(m2c, acc[nt][1], zq0 + zk.y));
        *(float2*)(zbase + 8 * SEQ + col) =
            make_float2(fmaf(m2c, acc[nt][2], zq1 + zk.x),
                        fmaf(m2c, acc[nt][3], zq1 + zk.y));
    }
}

// ---------------------------------------------------------------------------
// Accumulation: ctx[i,k] = sum_j max(v[j,k], z[i,j]) - sum_j z[i,j]
// CTA = (i-tile 32, head, j-part of 64), 128 threads. grid (16,8,8).
// ---------------------------------------------------------------------------
__global__ __launch_bounds__(128) void accum_kernel()
{
    __shared__ float zs[32][68];
    __shared__ float vs[64][68];

    int t = threadIdx.x;
    int i0 = blockIdx.x * 32, head = blockIdx.y, j0 = blockIdx.z * 64;

    int zr = t >> 2, zq4 = t & 3;
    const float* zp = g_z + ((size_t)head * SEQ + i0 + zr) * SEQ + j0 + zq4 * 16;
    int vr = t >> 1, vhh = t & 1;
    const float* vp = g_v + (j0 + vr) * HIDDEN + head * HD + vhh * 32;
#pragma unroll
    for (int c = 0; c < 4; c++)
        *(float4*)&zs[zr][zq4 * 16 + c * 4] = *(const float4*)(zp + c * 4);
#pragma unroll
    for (int c = 0; c < 8; c++)
        *(float4*)&vs[vr][vhh * 32 + c * 4] = *(const float4*)(vp + c * 4);
    __syncthreads();

    int il = t & 31, kq = t >> 5;
    float acc[16];
#pragma unroll
    for (int x = 0; x < 16; x++) acc[x] = 0.0f;
    float accz = 0.0f;

#pragma unroll 2
    for (int jb = 0; jb < 16; jb++) {
        float4 z4 = *(const float4*)&zs[il][jb * 4];
        float zarr[4] = {z4.x, z4.y, z4.z, z4.w};
#pragma unroll
        for (int e = 0; e < 4; e++) {
            float z = zarr[e];
            accz += z;
            int jj = jb * 4 + e;
#pragma unroll
            for (int cc = 0; cc < 4; cc++) {
                float4 v4 = *(const float4*)&vs[jj][kq * 16 + cc * 4];
                acc[cc * 4 + 0] += fmaxf(v4.x, z);
                acc[cc * 4 + 1] += fmaxf(v4.y, z);
                acc[cc * 4 + 2] += fmaxf(v4.z, z);
                acc[cc * 4 + 3] += fmaxf(v4.w, z);
            }
        }
    }

    float* outp = g_ctx[blockIdx.z] + (i0 + il) * HIDDEN + head * HD + kq * 16;
#pragma unroll
    for (int cc = 0; cc < 4; cc++)
        *(float4*)(outp + cc * 4) = make_float4(acc[cc * 4 + 0] - accz,
                                                acc[cc * 4 + 1] - accz,
                                                acc[cc * 4 + 2] - accz,
                                                acc[cc * 4 + 3] - accz);
}

// ---------------------------------------------------------------------------
// Reduce 8 partials and emit packed hi/lo planes of ctxsum. grid 512x256.
// ---------------------------------------------------------------------------
__global__ __launch_bounds__(256) void reduce_kernel()
{
    int idx = blockIdx.x * 256 + threadIdx.x;
    float2 s = make_float2(0.0f, 0.0f);
#pragma unroll
    for (int p = 0; p < NPART; p++) {
        float2 v = *(const float2*)&g_ctx[p][idx * 2];
        s.x += v.x; s.y += v.y;
    }
    unsigned h, l; split2(s.x, s.y, h, l);
    g_Ch[idx] = h; g_Cl[idx] = l;
}

extern "C" void kernel_launch(void* const* d_in, const int* in_sizes, int n_in,
                              void* d_out, int out_size)
{
    const float* X     = (const float*)d_in[0];
    const float* mask  = (const float*)d_in[1];
    const float* Wq    = (const float*)d_in[2];
    const float* bq    = (const float*)d_in[3];
    const float* Wk    = (const float*)d_in[4];
    const float* bk    = (const float*)d_in[5];
    const float* Wv    = (const float*)d_in[6];
    const float* bv    = (const float*)d_in[7];
    const float* Wo    = (const float*)d_in[8];
    const float* bo    = (const float*)d_in[9];
    const float* gamma = (const float*)d_in[10];
    float* out = (float*)d_out;

    convert_kernel<<<dim3(512, 1, 5), 256>>>(X, Wq, Wk, Wv, Wo);
    qkv_mma_kernel<<<dim3(8, 16, 3), 128>>>(bq, bk, bv);
    norm_kernel<<<32, 256>>>(mask, gamma);
    z_kernel<<<dim3(8, 8, 8), 256>>>(gamma);
    accum_kernel<<<dim3(16, 8, 8), 128>>>();
    reduce_kernel<<<512, 256>>>();
    out_mma_kernel<<<dim3(8, 16), 128>>>(bo, out);
}

// round 7
// speedup vs baseline: 1.9186x; 1.0942x over previous
#include <cuda_runtime.h>

#define SEQ 512
#define HIDDEN 512
#define HD 64
#define NPART 4

// ---------------------------------------------------------------------------
// Scratch (static __device__, no allocation)
// ---------------------------------------------------------------------------
__device__ unsigned g_Xh[SEQ * 256], g_Xl[SEQ * 256];
__device__ unsigned g_Wqh[SEQ * 256], g_Wql[SEQ * 256];
__device__ unsigned g_Wkh[SEQ * 256], g_Wkl[SEQ * 256];
__device__ unsigned g_Wvh[SEQ * 256], g_Wvl[SEQ * 256];
__device__ unsigned g_Woh[SEQ * 256], g_Wol[SEQ * 256];
__device__ float    g_q[SEQ * HIDDEN], g_k[SEQ * HIDDEN], g_v[SEQ * HIDDEN];
__device__ unsigned g_qh[SEQ * 256], g_ql[SEQ * 256];
__device__ unsigned g_kh[SEQ * 256], g_kl[SEQ * 256];
__device__ float    g_zq[8 * SEQ], g_zkm[8 * SEQ];
__device__ float    g_ctx[NPART][SEQ * HIDDEN];
__device__ unsigned g_Ch[SEQ * 256], g_Cl[SEQ * 256];

// ---------------------------------------------------------------------------
// bf16x3 split: hi = exact top-16 truncation, lo = rn_bf16(x - hi).
// ---------------------------------------------------------------------------
__device__ __forceinline__ void split2(float x0, float x1, unsigned& hi, unsigned& lo)
{
    unsigned u0 = __float_as_uint(x0), u1 = __float_as_uint(x1);
    unsigned h;
    asm("prmt.b32 %0, %1, %2, 0x7632;" : "=r"(h) : "r"(u0), "r"(u1));
    float l0 = x0 - __uint_as_float(u0 & 0xFFFF0000u);
    float l1 = x1 - __uint_as_float(u1 & 0xFFFF0000u);
    unsigned lp;
    asm("cvt.rn.bf16x2.f32 %0, %1, %2;" : "=r"(lp) : "f"(l1), "f"(l0));
    hi = h; lo = lp;
}

__device__ __forceinline__ void mma_bf16(float* c,
    unsigned a0, unsigned a1, unsigned a2, unsigned a3, unsigned b0, unsigned b1)
{
    asm("mma.sync.aligned.m16n8k16.row.col.f32.bf16.bf16.f32 "
        "{%0,%1,%2,%3}, {%4,%5,%6,%7}, {%8,%9}, {%0,%1,%2,%3};"
        : "+f"(c[0]), "+f"(c[1]), "+f"(c[2]), "+f"(c[3])
        : "r"(a0), "r"(a1), "r"(a2), "r"(a3), "r"(b0), "r"(b1));
}

__device__ __forceinline__ void cp16(void* dst, const void* src)
{
    unsigned d = (unsigned)__cvta_generic_to_shared(dst);
    asm volatile("cp.async.cg.shared.global [%0], [%1], 16;" :: "r"(d), "l"(src));
}
#define CP_COMMIT() asm volatile("cp.async.commit_group;")

// ---------------------------------------------------------------------------
// Convert: split 5 f32 matrices into packed hi/lo planes. grid (512,1,5)x256.
// ---------------------------------------------------------------------------
__global__ __launch_bounds__(256) void convert_kernel(
    const float* __restrict__ X, const float* __restrict__ Wq,
    const float* __restrict__ Wk, const float* __restrict__ Wv,
    const float* __restrict__ Wo)
{
    const float* src; unsigned* dh; unsigned* dl;
    switch (blockIdx.z) {
        case 0:  src = X;  dh = g_Xh;  dl = g_Xl;  break;
        case 1:  src = Wq; dh = g_Wqh; dl = g_Wql; break;
        case 2:  src = Wk; dh = g_Wkh; dl = g_Wkl; break;
        case 3:  src = Wv; dh = g_Wvh; dl = g_Wvl; break;
        default: src = Wo; dh = g_Woh; dl = g_Wol; break;
    }
    int idx = blockIdx.x * 256 + threadIdx.x;
    float2 v = *(const float2*)(src + idx * 2);
    unsigned h, l; split2(v.x, v.y, h, l);
    dh[idx] = h; dl[idx] = l;
}

// ---------------------------------------------------------------------------
// GEMM NT on pre-split planes (32x64 tile, cp.async 4-stage), as R6.
// ---------------------------------------------------------------------------
__device__ __forceinline__ void gemm_planes(
    const unsigned* __restrict__ Aph, const unsigned* __restrict__ Apl,
    const unsigned* __restrict__ Bph, const unsigned* __restrict__ Bpl,
    const float* __restrict__ bias, float* __restrict__ out,
    unsigned* __restrict__ outh, unsigned* __restrict__ outl)
{
    __shared__ unsigned smA[4][2][32][12];
    __shared__ unsigned smB[4][2][64][12];

    int t = threadIdx.x;
    int row0 = blockIdx.y * 32, col0 = blockIdx.x * 64;
    int lane = t & 31, warp = t >> 5;
    int wm = warp >> 1, wn = warp & 1;
    int g = lane >> 2, tq = lane & 3;

    int p = t >> 6;
    int ar = (t >> 1) & 31, ahalf = t & 1;
    int br = t & 63;

    const unsigned* Asrc = (p ? Apl : Aph) + (row0 + ar) * 256 + ahalf * 4;
    const unsigned* Bsrc = (p ? Bpl : Bph) + (col0 + br) * 256;

    float acc[4][4];
#pragma unroll
    for (int nt = 0; nt < 4; nt++)
#pragma unroll
        for (int x = 0; x < 4; x++) acc[nt][x] = 0.0f;

#pragma unroll
    for (int s = 0; s < 3; s++) {
        cp16(&smA[s][p][ar][ahalf * 4], Asrc + s * 8);
        cp16(&smB[s][p][br][0], Bsrc + s * 8);
        cp16(&smB[s][p][br][4], Bsrc + s * 8 + 4);
        CP_COMMIT();
    }

#pragma unroll 1
    for (int kb = 0; kb < 32; kb++) {
        asm volatile("cp.async.wait_group 2;");
        __syncthreads();
        if (kb + 3 < 32) {
            int s = (kb + 3) & 3;
            cp16(&smA[s][p][ar][ahalf * 4], Asrc + (kb + 3) * 8);
            cp16(&smB[s][p][br][0], Bsrc + (kb + 3) * 8);
            cp16(&smB[s][p][br][4], Bsrc + (kb + 3) * 8 + 4);
        }
        CP_COMMIT();

        int st = kb & 3;
        int r = wm * 16 + g;
        unsigned ah0 = smA[st][0][r][tq],     ah1 = smA[st][0][r + 8][tq];
        unsigned ah2 = smA[st][0][r][tq + 4], ah3 = smA[st][0][r + 8][tq + 4];
        unsigned al0 = smA[st][1][r][tq],     al1 = smA[st][1][r + 8][tq];
        unsigned al2 = smA[st][1][r][tq + 4], al3 = smA[st][1][r + 8][tq + 4];
#pragma unroll
        for (int nt = 0; nt < 4; nt++) {
            int n = wn * 32 + nt * 8 + g;
            unsigned bh0 = smB[st][0][n][tq], bh1 = smB[st][0][n][tq + 4];
            unsigned bl0 = smB[st][1][n][tq], bl1 = smB[st][1][n][tq + 4];
            mma_bf16(acc[nt], ah0, ah1, ah2, ah3, bh0, bh1);
            mma_bf16(acc[nt], ah0, ah1, ah2, ah3, bl0, bl1);
            mma_bf16(acc[nt], al0, al1, al2, al3, bh0, bh1);
        }
    }
    asm volatile("cp.async.wait_group 0;");

#pragma unroll
    for (int nt = 0; nt < 4; nt++) {
        int row = row0 + wm * 16 + g;
        int col = col0 + wn * 32 + nt * 8 + 2 * tq;
        float2 b2 = *(const float2*)(bias + col);
        float v0 = acc[nt][0] + b2.x, v1 = acc[nt][1] + b2.y;
        float v2 = acc[nt][2] + b2.x, v3 = acc[nt][3] + b2.y;
        *(float2*)(out + row * HIDDEN + col) = make_float2(v0, v1);
        *(float2*)(out + (row + 8) * HIDDEN + col) = make_float2(v2, v3);
        if (outh) {
            unsigned h, l;
            split2(v0, v1, h, l);
            outh[row * 256 + (col >> 1)] = h; outl[row * 256 + (col >> 1)] = l;
            split2(v2, v3, h, l);
            outh[(row + 8) * 256 + (col >> 1)] = h; outl[(row + 8) * 256 + (col >> 1)] = l;
        }
    }
}

__global__ __launch_bounds__(128) void qkv_mma_kernel(
    const float* __restrict__ bq, const float* __restrict__ bk,
    const float* __restrict__ bv)
{
    if (blockIdx.z == 0)
        gemm_planes(g_Xh, g_Xl, g_Wqh, g_Wql, bq, g_q, g_qh, g_ql);
    else if (blockIdx.z == 1)
        gemm_planes(g_Xh, g_Xl, g_Wkh, g_Wkl, bk, g_k, g_kh, g_kl);
    else
        gemm_planes(g_Xh, g_Xl, g_Wvh, g_Wvl, bv, g_v, (unsigned*)0, (unsigned*)0);
}

__global__ __launch_bounds__(128) void out_mma_kernel(
    const float* __restrict__ bo, float* __restrict__ out)
{
    gemm_planes(g_Ch, g_Cl, g_Woh, g_Wol, bo, out, (unsigned*)0, (unsigned*)0);
}

// ---------------------------------------------------------------------------
// Norms: zq[h][i] = coef*|q|^2 ; zkm[h][j] = coef*|k|^2 + zc + (1-mask)*1e10
// ---------------------------------------------------------------------------
__global__ __launch_bounds__(256) void norm_kernel(
    const float* __restrict__ mask, const float* __restrict__ gamma)
{
    int id = blockIdx.x * 256 + threadIdx.x;
    int which = id >> 12, head = (id >> 9) & 7, row = id & 511;
    const float* src = (which ? g_k : g_q) + row * HIDDEN + head * HD;
    float s = 0.0f;
#pragma unroll
    for (int c = 0; c < 16; c++) {
        float4 f = *(const float4*)(src + c * 4);
        s = fmaf(f.x, f.x, s); s = fmaf(f.y, f.y, s);
        s = fmaf(f.z, f.z, s); s = fmaf(f.w, f.w, s);
    }
    float gsd = gamma[0] * 8.0f;
    float coef = 15.0f / (16.0f * gsd);
    float zc = 12.0f / gsd;
    if (which)
        g_zkm[head * SEQ + row] = fmaf(coef, s, zc + (1.0f - mask[row]) * 1e10f);
    else
        g_zq[head * SEQ + row] = coef * s;
}

// ---------------------------------------------------------------------------
// FUSED inhibitor: CTA = (i-tile 64, head, j-part 128), 256 threads (8 warps).
// Per 32-j chunk: MMA z-tile (bf16x3, warp grid 4m x 2n, warp tile 16x16),
// affine epilogue -> zs smem, then ctx += max(v,z), accz += z. z never hits
// global memory. ctx[i,k] = sum_j max(v,z) - sum_j z.
// ---------------------------------------------------------------------------
__global__ __launch_bounds__(256) void fused_kernel(const float* __restrict__ gamma)
{
    __shared__ unsigned smq[2][64][36];  // q hi/lo planes [row][packed-k]
    __shared__ unsigned smk[2][32][36];  // k chunk planes
    __shared__ float vs[32][68];         // v chunk [j][k]
    __shared__ float zs[64][33];         // z tile [i][j]

    int t = threadIdx.x;
    int i0 = blockIdx.x * 64, head = blockIdx.y, jp = blockIdx.z;
    int j0 = jp * 128;

    // stage q planes (cp.async): 2 planes x 64 rows x 32 u32
    {
        int p = t >> 7, row = (t >> 1) & 63, half = t & 1;
        const unsigned* src = (p ? g_ql : g_qh) + (i0 + row) * 256 + head * 32 + half * 16;
#pragma unroll
        for (int s = 0; s < 4; s++)
            cp16(&smq[p][row][half * 16 + s * 4], src + s * 4);
        CP_COMMIT();
    }

    // prefetch chunk 0: k planes + v (registers)
    int kp = t >> 7, krow = (t >> 2) & 31, kq4 = t & 3;
    const unsigned* kplane = kp ? g_kl : g_kh;
    uint4 kr0, kr1;
    {
        const unsigned* s0 = kplane + (j0 + krow) * 256 + head * 32 + kq4 * 8;
        kr0 = *(const uint4*)(s0); kr1 = *(const uint4*)(s0 + 4);
    }
    int vrow = t >> 3, vseg = t & 7;
    float4 vr0, vr1;
    {
        const float* s0 = g_v + (j0 + vrow) * HIDDEN + head * HD + vseg * 8;
        vr0 = *(const float4*)(s0); vr1 = *(const float4*)(s0 + 4);
    }

    int lane = t & 31, warp = t >> 5;
    int wm = warp >> 1, wn = warp & 1;
    int g = lane >> 2, tq = lane & 3;

    float gsd = gamma[0] * 8.0f;
    float m2c = -2.0f * 15.0f / (16.0f * gsd);
    float zq0 = g_zq[head * SEQ + i0 + wm * 16 + g];
    float zq1 = g_zq[head * SEQ + i0 + wm * 16 + g + 8];

    int il = (t & 31) + ((warp & 1) << 5);   // accum: i-local; v reads broadcast
    int kq = t >> 6;                         // accum: k-quarter

    float acc[16];
#pragma unroll
    for (int x = 0; x < 16; x++) acc[x] = 0.0f;
    float accz = 0.0f;

    asm volatile("cp.async.wait_group 0;");

#pragma unroll 1
    for (int c = 0; c < 4; c++) {
        __syncthreads();   // prev chunk consumers done; q visible (c=0)
        *(uint4*)&smk[kp][krow][kq4 * 8]     = kr0;
        *(uint4*)&smk[kp][krow][kq4 * 8 + 4] = kr1;
        *(float4*)&vs[vrow][vseg * 8]     = vr0;
        *(float4*)&vs[vrow][vseg * 8 + 4] = vr1;
        if (c < 3) {
            const unsigned* s0 = kplane + (j0 + (c + 1) * 32 + krow) * 256 + head * 32 + kq4 * 8;
            kr0 = *(const uint4*)(s0); kr1 = *(const uint4*)(s0 + 4);
            const float* sv = g_v + (j0 + (c + 1) * 32 + vrow) * HIDDEN + head * HD + vseg * 8;
            vr0 = *(const float4*)(sv); vr1 = *(const float4*)(sv + 4);
        }
        __syncthreads();

        // z = m2c*(q.k) + zq[i] + zkm[j] via mma, into zs
        {
            float za[2][4];
#pragma unroll
            for (int nt = 0; nt < 2; nt++)
#pragma unroll
                for (int x = 0; x < 4; x++) za[nt][x] = 0.0f;

            int r = wm * 16 + g;
#pragma unroll
            for (int kb = 0; kb < 4; kb++) {
                int base = kb * 8;
                unsigned ah0 = smq[0][r][base + tq],     ah1 = smq[0][r + 8][base + tq];
                unsigned ah2 = smq[0][r][base + tq + 4], ah3 = smq[0][r + 8][base + tq + 4];
                unsigned al0 = smq[1][r][base + tq],     al1 = smq[1][r + 8][base + tq];
                unsigned al2 = smq[1][r][base + tq + 4], al3 = smq[1][r + 8][base + tq + 4];
#pragma unroll
                for (int nt = 0; nt < 2; nt++) {
                    int n = wn * 16 + nt * 8 + g;
                    unsigned bh0 = smk[0][n][base + tq], bh1 = smk[0][n][base + tq + 4];
                    unsigned bl0 = smk[1][n][base + tq], bl1 = smk[1][n][base + tq + 4];
                    mma_bf16(za[nt], ah0, ah1, ah2, ah3, bh0, bh1);
                    mma_bf16(za[nt], ah0, ah1, ah2, ah3, bl0, bl1);
                    mma_bf16(za[nt], al0, al1, al2, al3, bh0, bh1);
                }
            }
#pragma unroll
            for (int nt = 0; nt < 2; nt++) {
                int col = wn * 16 + nt * 8 + 2 * tq;
                float2 zk = *(const float2*)(g_zkm + head * SEQ + j0 + c * 32 + col);
                zs[r][col]         = fmaf(m2c, za[nt][0], zq0 + zk.x);
                zs[r][col + 1]     = fmaf(m2c, za[nt][1], zq0 + zk.y);
                zs[r + 8][col]     = fmaf(m2c, za[nt][2], zq1 + zk.x);
                zs[r + 8][col + 1] = fmaf(m2c, za[nt][3], zq1 + zk.y);
            }
        }
        __syncthreads();

        // accumulation: ctx += max(v, z); accz += z
#pragma unroll 4
        for (int jj = 0; jj < 32; jj++) {
            float z = zs[il][jj];
            accz += z;
#pragma unroll
            for (int cc = 0; cc < 4; cc++) {
                float4 v4 = *(const float4*)&vs[jj][kq * 16 + cc * 4];
                acc[cc * 4 + 0] += fmaxf(v4.x, z);
                acc[cc * 4 + 1] += fmaxf(v4.y, z);
                acc[cc * 4 + 2] += fmaxf(v4.z, z);
                acc[cc * 4 + 3] += fmaxf(v4.w, z);
            }
        }
    }

    float* outp = g_ctx[jp] + (i0 + il) * HIDDEN + head * HD + kq * 16;
#pragma unroll
    for (int cc = 0; cc < 4; cc++)
        *(float4*)(outp + cc * 4) = make_float4(acc[cc * 4 + 0] - accz,
                                                acc[cc * 4 + 1] - accz,
                                                acc[cc * 4 + 2] - accz,
                                                acc[cc * 4 + 3] - accz);
}

// ---------------------------------------------------------------------------
// Reduce 4 partials and emit packed hi/lo planes of ctxsum. grid 512x256.
// ---------------------------------------------------------------------------
__global__ __launch_bounds__(256) void reduce_kernel()
{
    int idx = blockIdx.x * 256 + threadIdx.x;
    float2 s = make_float2(0.0f, 0.0f);
#pragma unroll
    for (int p = 0; p < NPART; p++) {
        float2 v = *(const float2*)&g_ctx[p][idx * 2];
        s.x += v.x; s.y += v.y;
    }
    unsigned h, l; split2(s.x, s.y, h, l);
    g_Ch[idx] = h; g_Cl[idx] = l;
}

extern "C" void kernel_launch(void* const* d_in, const int* in_sizes, int n_in,
                              void* d_out, int out_size)
{
    const float* X     = (const float*)d_in[0];
    const float* mask  = (const float*)d_in[1];
    const float* bq    = (const float*)d_in[3];
    const float* bk    = (const float*)d_in[5];
    const float* bv    = (const float*)d_in[7];
    const float* bo    = (const float*)d_in[9];
    const float* gamma = (const float*)d_in[10];
    const float* Wq    = (const float*)d_in[2];
    const float* Wk    = (const float*)d_in[4];
    const float* Wv    = (const float*)d_in[6];
    const float* Wo    = (const float*)d_in[8];
    float* out = (float*)d_out;

    convert_kernel<<<dim3(512, 1, 5), 256>>>(X, Wq, Wk, Wv, Wo);
    qkv_mma_kernel<<<dim3(8, 16, 3), 128>>>(bq, bk, bv);
    norm_kernel<<<32, 256>>>(mask, gamma);
    fused_kernel<<<dim3(8, 8, NPART), 256>>>(gamma);
    reduce_kernel<<<512, 256>>>();
    out_mma_kernel<<<dim3(8, 16), 128>>>(bo, out);
}

// round 8
// speedup vs baseline: 1.9795x; 1.0317x over previous
#include <cuda_runtime.h>

#define SEQ 512
#define HIDDEN 512
#define HD 64
#define NPART 4

// ---------------------------------------------------------------------------
// Scratch (static __device__, no allocation)
// ---------------------------------------------------------------------------
__device__ unsigned g_Xh[SEQ * 256], g_Xl[SEQ * 256];
__device__ unsigned g_Wqh[SEQ * 256], g_Wql[SEQ * 256];
__device__ unsigned g_Wkh[SEQ * 256], g_Wkl[SEQ * 256];
__device__ unsigned g_Wvh[SEQ * 256], g_Wvl[SEQ * 256];
__device__ unsigned g_Woh[SEQ * 256], g_Wol[SEQ * 256];
__device__ float    g_q[SEQ * HIDDEN], g_k[SEQ * HIDDEN], g_v[SEQ * HIDDEN];
__device__ unsigned g_qh[SEQ * 256], g_ql[SEQ * 256];
__device__ unsigned g_kh[SEQ * 256], g_kl[SEQ * 256];
__device__ float    g_zq[8 * SEQ], g_zkm[8 * SEQ];
__device__ float    g_ctx[NPART][SEQ * HIDDEN];
__device__ unsigned g_Ch[SEQ * 256], g_Cl[SEQ * 256];

// ---------------------------------------------------------------------------
// bf16x3 split + mma + cp.async helpers
// ---------------------------------------------------------------------------
__device__ __forceinline__ void split2(float x0, float x1, unsigned& hi, unsigned& lo)
{
    unsigned u0 = __float_as_uint(x0), u1 = __float_as_uint(x1);
    unsigned h;
    asm("prmt.b32 %0, %1, %2, 0x7632;" : "=r"(h) : "r"(u0), "r"(u1));
    float l0 = x0 - __uint_as_float(u0 & 0xFFFF0000u);
    float l1 = x1 - __uint_as_float(u1 & 0xFFFF0000u);
    unsigned lp;
    asm("cvt.rn.bf16x2.f32 %0, %1, %2;" : "=r"(lp) : "f"(l1), "f"(l0));
    hi = h; lo = lp;
}

__device__ __forceinline__ void mma_bf16(float* c,
    unsigned a0, unsigned a1, unsigned a2, unsigned a3, unsigned b0, unsigned b1)
{
    asm("mma.sync.aligned.m16n8k16.row.col.f32.bf16.bf16.f32 "
        "{%0,%1,%2,%3}, {%4,%5,%6,%7}, {%8,%9}, {%0,%1,%2,%3};"
        : "+f"(c[0]), "+f"(c[1]), "+f"(c[2]), "+f"(c[3])
        : "r"(a0), "r"(a1), "r"(a2), "r"(a3), "r"(b0), "r"(b1));
}

__device__ __forceinline__ void cp16(void* dst, const void* src)
{
    unsigned d = (unsigned)__cvta_generic_to_shared(dst);
    asm volatile("cp.async.cg.shared.global [%0], [%1], 16;" :: "r"(d), "l"(src));
}
#define CP_COMMIT() asm volatile("cp.async.commit_group;")

// packed f32x2: acc += pack(a,b) * (1,1)   [fma pipe, 2 elements/instr]
__device__ __forceinline__ void fma2_acc(unsigned long long& acc, float a, float b,
                                         unsigned long long one2)
{
    asm("{\n\t.reg .b64 p;\n\tmov.b64 p, {%1,%2};\n\tfma.rn.f32x2 %0, p, %3, %0;\n\t}"
        : "+l"(acc) : "f"(a), "f"(b), "l"(one2));
}
__device__ __forceinline__ void add2_acc(unsigned long long& acc, float a, float b)
{
    asm("{\n\t.reg .b64 p;\n\tmov.b64 p, {%1,%2};\n\tadd.rn.f32x2 %0, %0, p;\n\t}"
        : "+l"(acc) : "f"(a), "f"(b));
}
__device__ __forceinline__ void unpack2(unsigned long long v, float& lo, float& hi)
{
    asm("mov.b64 {%0,%1}, %2;" : "=f"(lo), "=f"(hi) : "l"(v));
}

// ---------------------------------------------------------------------------
// Convert: split 5 f32 matrices into packed hi/lo planes. grid (512,1,5)x256.
// ---------------------------------------------------------------------------
__global__ __launch_bounds__(256) void convert_kernel(
    const float* __restrict__ X, const float* __restrict__ Wq,
    const float* __restrict__ Wk, const float* __restrict__ Wv,
    const float* __restrict__ Wo)
{
    const float* src; unsigned* dh; unsigned* dl;
    switch (blockIdx.z) {
        case 0:  src = X;  dh = g_Xh;  dl = g_Xl;  break;
        case 1:  src = Wq; dh = g_Wqh; dl = g_Wql; break;
        case 2:  src = Wk; dh = g_Wkh; dl = g_Wkl; break;
        case 3:  src = Wv; dh = g_Wvh; dl = g_Wvl; break;
        default: src = Wo; dh = g_Woh; dl = g_Wol; break;
    }
    int idx = blockIdx.x * 256 + threadIdx.x;
    float2 v = *(const float2*)(src + idx * 2);
    unsigned h, l; split2(v.x, v.y, h, l);
    dh[idx] = h; dl[idx] = l;
}

// ---------------------------------------------------------------------------
// GEMM NT on pre-split planes (32x64 tile, cp.async 4-stage), as R6/R7.
// ---------------------------------------------------------------------------
__device__ __forceinline__ void gemm_planes(
    const unsigned* __restrict__ Aph, const unsigned* __restrict__ Apl,
    const unsigned* __restrict__ Bph, const unsigned* __restrict__ Bpl,
    const float* __restrict__ bias, float* __restrict__ out,
    unsigned* __restrict__ outh, unsigned* __restrict__ outl)
{
    __shared__ unsigned smA[4][2][32][12];
    __shared__ unsigned smB[4][2][64][12];

    int t = threadIdx.x;
    int row0 = blockIdx.y * 32, col0 = blockIdx.x * 64;
    int lane = t & 31, warp = t >> 5;
    int wm = warp >> 1, wn = warp & 1;
    int g = lane >> 2, tq = lane & 3;

    int p = t >> 6;
    int ar = (t >> 1) & 31, ahalf = t & 1;
    int br = t & 63;

    const unsigned* Asrc = (p ? Apl : Aph) + (row0 + ar) * 256 + ahalf * 4;
    const unsigned* Bsrc = (p ? Bpl : Bph) + (col0 + br) * 256;

    float acc[4][4];
#pragma unroll
    for (int nt = 0; nt < 4; nt++)
#pragma unroll
        for (int x = 0; x < 4; x++) acc[nt][x] = 0.0f;

#pragma unroll
    for (int s = 0; s < 3; s++) {
        cp16(&smA[s][p][ar][ahalf * 4], Asrc + s * 8);
        cp16(&smB[s][p][br][0], Bsrc + s * 8);
        cp16(&smB[s][p][br][4], Bsrc + s * 8 + 4);
        CP_COMMIT();
    }

#pragma unroll 1
    for (int kb = 0; kb < 32; kb++) {
        asm volatile("cp.async.wait_group 2;");
        __syncthreads();
        if (kb + 3 < 32) {
            int s = (kb + 3) & 3;
            cp16(&smA[s][p][ar][ahalf * 4], Asrc + (kb + 3) * 8);
            cp16(&smB[s][p][br][0], Bsrc + (kb + 3) * 8);
            cp16(&smB[s][p][br][4], Bsrc + (kb + 3) * 8 + 4);
        }
        CP_COMMIT();

        int st = kb & 3;
        int r = wm * 16 + g;
        unsigned ah0 = smA[st][0][r][tq],     ah1 = smA[st][0][r + 8][tq];
        unsigned ah2 = smA[st][0][r][tq + 4], ah3 = smA[st][0][r + 8][tq + 4];
        unsigned al0 = smA[st][1][r][tq],     al1 = smA[st][1][r + 8][tq];
        unsigned al2 = smA[st][1][r][tq + 4], al3 = smA[st][1][r + 8][tq + 4];
#pragma unroll
        for (int nt = 0; nt < 4; nt++) {
            int n = wn * 32 + nt * 8 + g;
            unsigned bh0 = smB[st][0][n][tq], bh1 = smB[st][0][n][tq + 4];
            unsigned bl0 = smB[st][1][n][tq], bl1 = smB[st][1][n][tq + 4];
            mma_bf16(acc[nt], ah0, ah1, ah2, ah3, bh0, bh1);
            mma_bf16(acc[nt], ah0, ah1, ah2, ah3, bl0, bl1);
            mma_bf16(acc[nt], al0, al1, al2, al3, bh0, bh1);
        }
    }
    asm volatile("cp.async.wait_group 0;");

#pragma unroll
    for (int nt = 0; nt < 4; nt++) {
        int row = row0 + wm * 16 + g;
        int col = col0 + wn * 32 + nt * 8 + 2 * tq;
        float2 b2 = *(const float2*)(bias + col);
        float v0 = acc[nt][0] + b2.x, v1 = acc[nt][1] + b2.y;
        float v2 = acc[nt][2] + b2.x, v3 = acc[nt][3] + b2.y;
        *(float2*)(out + row * HIDDEN + col) = make_float2(v0, v1);
        *(float2*)(out + (row + 8) * HIDDEN + col) = make_float2(v2, v3);
        if (outh) {
            unsigned h, l;
            split2(v0, v1, h, l);
            outh[row * 256 + (col >> 1)] = h; outl[row * 256 + (col >> 1)] = l;
            split2(v2, v3, h, l);
            outh[(row + 8) * 256 + (col >> 1)] = h; outl[(row + 8) * 256 + (col >> 1)] = l;
        }
    }
}

__global__ __launch_bounds__(128) void qkv_mma_kernel(
    const float* __restrict__ bq, const float* __restrict__ bk,
    const float* __restrict__ bv)
{
    if (blockIdx.z == 0)
        gemm_planes(g_Xh, g_Xl, g_Wqh, g_Wql, bq, g_q, g_qh, g_ql);
    else if (blockIdx.z == 1)
        gemm_planes(g_Xh, g_Xl, g_Wkh, g_Wkl, bk, g_k, g_kh, g_kl);
    else
        gemm_planes(g_Xh, g_Xl, g_Wvh, g_Wvl, bv, g_v, (unsigned*)0, (unsigned*)0);
}

__global__ __launch_bounds__(128) void out_mma_kernel(
    const float* __restrict__ bo, float* __restrict__ out)
{
    gemm_planes(g_Ch, g_Cl, g_Woh, g_Wol, bo, out, (unsigned*)0, (unsigned*)0);
}

// ---------------------------------------------------------------------------
// Norms: zq[h][i] = coef*|q|^2 ; zkm[h][j] = coef*|k|^2 + zc + (1-mask)*1e10
// ---------------------------------------------------------------------------
__global__ __launch_bounds__(256) void norm_kernel(
    const float* __restrict__ mask, const float* __restrict__ gamma)
{
    int id = blockIdx.x * 256 + threadIdx.x;
    int which = id >> 12, head = (id >> 9) & 7, row = id & 511;
    const float* src = (which ? g_k : g_q) + row * HIDDEN + head * HD;
    float s = 0.0f;
#pragma unroll
    for (int c = 0; c < 16; c++) {
        float4 f = *(const float4*)(src + c * 4);
        s = fmaf(f.x, f.x, s); s = fmaf(f.y, f.y, s);
        s = fmaf(f.z, f.z, s); s = fmaf(f.w, f.w, s);
    }
    float gsd = gamma[0] * 8.0f;
    float coef = 15.0f / (16.0f * gsd);
    float zc = 12.0f / gsd;
    if (which)
        g_zkm[head * SEQ + row] = fmaf(coef, s, zc + (1.0f - mask[row]) * 1e10f);
    else
        g_zq[head * SEQ + row] = coef * s;
}

// ---------------------------------------------------------------------------
// FUSED inhibitor: CTA = (i-tile 64, head, j-part 128), 256 threads (8 warps).
// Per 32-j chunk: MMA z-tile (bf16x3) -> affine epilogue -> zst (TRANSPOSED
// [j][i]) -> streaming accumulation with 4i x 4k per-thread tile and packed
// f32x2 accumulators. ctx[i,k] = sum_j max(v,z) - sum_j z.
// ---------------------------------------------------------------------------
__global__ __launch_bounds__(256) void fused_kernel(const float* __restrict__ gamma)
{
    __shared__ unsigned smq[2][64][36];  // q hi/lo planes [row][packed-k]
    __shared__ unsigned smk[2][32][36];  // k chunk planes
    __shared__ float vs[32][68];         // v chunk [j][k]
    __shared__ float zst[32][68];        // z tile TRANSPOSED [j][i]

    int t = threadIdx.x;
    int i0 = blockIdx.x * 64, head = blockIdx.y, jp = blockIdx.z;
    int j0 = jp * 128;

    // stage q planes (cp.async)
    {
        int p = t >> 7, row = (t >> 1) & 63, half = t & 1;
        const unsigned* src = (p ? g_ql : g_qh) + (i0 + row) * 256 + head * 32 + half * 16;
#pragma unroll
        for (int s = 0; s < 4; s++)
            cp16(&smq[p][row][half * 16 + s * 4], src + s * 4);
        CP_COMMIT();
    }

    // prefetch chunk 0: k planes + v (registers)
    int kp = t >> 7, krow = (t >> 2) & 31, kq4 = t & 3;
    const unsigned* kplane = kp ? g_kl : g_kh;
    uint4 kr0, kr1;
    {
        const unsigned* s0 = kplane + (j0 + krow) * 256 + head * 32 + kq4 * 8;
        kr0 = *(const uint4*)(s0); kr1 = *(const uint4*)(s0 + 4);
    }
    int vrow = t >> 3, vseg = t & 7;
    float4 vr0, vr1;
    {
        const float* s0 = g_v + (j0 + vrow) * HIDDEN + head * HD + vseg * 8;
        vr0 = *(const float4*)(s0); vr1 = *(const float4*)(s0 + 4);
    }

    int lane = t & 31, warp = t >> 5;
    int wm = warp >> 1, wn = warp & 1;
    int g = lane >> 2, tq = lane & 3;

    float gsd = gamma[0] * 8.0f;
    float m2c = -2.0f * 15.0f / (16.0f * gsd);
    float zq0 = g_zq[head * SEQ + i0 + wm * 16 + g];
    float zq1 = g_zq[head * SEQ + i0 + wm * 16 + g + 8];

    // accumulation mapping: 4i x 4k per thread
    int ig = t >> 4, kg = t & 15;

    const unsigned long long one2 = 0x3F8000003F800000ULL;
    unsigned long long acc2[4][2];
#pragma unroll
    for (int a = 0; a < 4; a++) { acc2[a][0] = 0ULL; acc2[a][1] = 0ULL; }
    unsigned long long accz01 = 0ULL, accz23 = 0ULL;

    asm volatile("cp.async.wait_group 0;");

#pragma unroll 1
    for (int c = 0; c < 4; c++) {
        __syncthreads();   // prev chunk consumers done; q visible (c=0)
        *(uint4*)&smk[kp][krow][kq4 * 8]     = kr0;
        *(uint4*)&smk[kp][krow][kq4 * 8 + 4] = kr1;
        *(float4*)&vs[vrow][vseg * 8]     = vr0;
        *(float4*)&vs[vrow][vseg * 8 + 4] = vr1;
        if (c < 3) {
            const unsigned* s0 = kplane + (j0 + (c + 1) * 32 + krow) * 256 + head * 32 + kq4 * 8;
            kr0 = *(const uint4*)(s0); kr1 = *(const uint4*)(s0 + 4);
            const float* sv = g_v + (j0 + (c + 1) * 32 + vrow) * HIDDEN + head * HD + vseg * 8;
            vr0 = *(const float4*)(sv); vr1 = *(const float4*)(sv + 4);
        }
        __syncthreads();

        // z = m2c*(q.k) + zq[i] + zkm[j] via mma, into zst (transposed)
        {
            float za[2][4];
#pragma unroll
            for (int nt = 0; nt < 2; nt++)
#pragma unroll
                for (int x = 0; x < 4; x++) za[nt][x] = 0.0f;

            int r = wm * 16 + g;
#pragma unroll
            for (int kb = 0; kb < 4; kb++) {
                int base = kb * 8;
                unsigned ah0 = smq[0][r][base + tq],     ah1 = smq[0][r + 8][base + tq];
                unsigned ah2 = smq[0][r][base + tq + 4], ah3 = smq[0][r + 8][base + tq + 4];
                unsigned al0 = smq[1][r][base + tq],     al1 = smq[1][r + 8][base + tq];
                unsigned al2 = smq[1][r][base + tq + 4], al3 = smq[1][r + 8][base + tq + 4];
#pragma unroll
                for (int nt = 0; nt < 2; nt++) {
                    int n = wn * 16 + nt * 8 + g;
                    unsigned bh0 = smk[0][n][base + tq], bh1 = smk[0][n][base + tq + 4];
                    unsigned bl0 = smk[1][n][base + tq], bl1 = smk[1][n][base + tq + 4];
                    mma_bf16(za[nt], ah0, ah1, ah2, ah3, bh0, bh1);
                    mma_bf16(za[nt], ah0, ah1, ah2, ah3, bl0, bl1);
                    mma_bf16(za[nt], al0, al1, al2, al3, bh0, bh1);
                }
            }
#pragma unroll
            for (int nt = 0; nt < 2; nt++) {
                int col = wn * 16 + nt * 8 + 2 * tq;
                float2 zk = *(const float2*)(g_zkm + head * SEQ + j0 + c * 32 + col);
                zst[col][r]         = fmaf(m2c, za[nt][0], zq0 + zk.x);
                zst[col + 1][r]     = fmaf(m2c, za[nt][1], zq0 + zk.y);
                zst[col][r + 8]     = fmaf(m2c, za[nt][2], zq1 + zk.x);
                zst[col + 1][r + 8] = fmaf(m2c, za[nt][3], zq1 + zk.y);
            }
        }
        __syncthreads();

        // accumulation: acc2 += max(v, z) (packed); accz += z (packed)
#pragma unroll 4
        for (int jj = 0; jj < 32; jj++) {
            float4 z4 = *(const float4*)&zst[jj][ig * 4];
            float4 v4 = *(const float4*)&vs[jj][kg * 4];
            add2_acc(accz01, z4.x, z4.y);
            add2_acc(accz23, z4.z, z4.w);
            float za[4] = {z4.x, z4.y, z4.z, z4.w};
#pragma unroll
            for (int a = 0; a < 4; a++) {
                float z = za[a];
                fma2_acc(acc2[a][0], fmaxf(v4.x, z), fmaxf(v4.y, z), one2);
                fma2_acc(acc2[a][1], fmaxf(v4.z, z), fmaxf(v4.w, z), one2);
            }
        }
    }

    float az[4];
    unpack2(accz01, az[0], az[1]);
    unpack2(accz23, az[2], az[3]);
#pragma unroll
    for (int a = 0; a < 4; a++) {
        float a0, a1, a2, a3;
        unpack2(acc2[a][0], a0, a1);
        unpack2(acc2[a][1], a2, a3);
        float* outp = g_ctx[jp] + (i0 + ig * 4 + a) * HIDDEN + head * HD + kg * 4;
        *(float4*)outp = make_float4(a0 - az[a], a1 - az[a], a2 - az[a], a3 - az[a]);
    }
}

// ---------------------------------------------------------------------------
// Reduce 4 partials and emit packed hi/lo planes of ctxsum. grid 512x256.
// ---------------------------------------------------------------------------
__global__ __launch_bounds__(256) void reduce_kernel()
{
    int idx = blockIdx.x * 256 + threadIdx.x;
    float2 s = make_float2(0.0f, 0.0f);
#pragma unroll
    for (int p = 0; p < NPART; p++) {
        float2 v = *(const float2*)&g_ctx[p][idx * 2];
        s.x += v.x; s.y += v.y;
    }
    unsigned h, l; split2(s.x, s.y, h, l);
    g_Ch[idx] = h; g_Cl[idx] = l;
}

extern "C" void kernel_launch(void* const* d_in, const int* in_sizes, int n_in,
                              void* d_out, int out_size)
{
    const float* X     = (const float*)d_in[0];
    const float* mask  = (const float*)d_in[1];
    const float* Wq    = (const float*)d_in[2];
    const float* bq    = (const float*)d_in[3];
    const float* Wk    = (const float*)d_in[4];
    const float* bk    = (const float*)d_in[5];
    const float* Wv    = (const float*)d_in[6];
    const float* bv    = (const float*)d_in[7];
    const float* Wo    = (const float*)d_in[8];
    const float* bo    = (const float*)d_in[9];
    const float* gamma = (const float*)d_in[10];
    float* out = (float*)d_out;

    convert_kernel<<<dim3(512, 1, 5), 256>>>(X, Wq, Wk, Wv, Wo);
    qkv_mma_kernel<<<dim3(8, 16, 3), 128>>>(bq, bk, bv);
    norm_kernel<<<32, 256>>>(mask, gamma);
    fused_kernel<<<dim3(8, 8, NPART), 256>>>(gamma);
    reduce_kernel<<<512, 256>>>();
    out_mma_kernel<<<dim3(8, 16), 128>>>(bo, out);
}